// round 1
// baseline (speedup 1.0000x reference)
#include <cuda_runtime.h>
#include <cuda_bf16.h>
#include <float.h>

// Problem constants
#define B_   4
#define S_   2048
#define DIN  1024
#define DINNER 1024
#define DOUT 1024
#define M1   (B_ * S_)          // 8192
#define N1   (3 * DINNER)       // 3072

// GEMM tile config
#define BM 128
#define BN 128
#define BK 16
#define TM 8
#define TN 8
#define NTHREADS 256

// ---------------------------------------------------------------------------
// Scratch (static device globals — no allocation in kernel_launch)
// ---------------------------------------------------------------------------
__device__ float g_qkv[(size_t)M1 * N1];          // 96 MB  [8192, 3072]
__device__ float g_sim[(size_t)B_ * S_ * S_];     // 64 MB  [4, 2048, 2048] (reused as attn)
__device__ float g_inner[(size_t)M1 * DINNER];    // 32 MB  [8192, 1024]

// ---------------------------------------------------------------------------
// Generic NN GEMM: C[M,N] = A[M,K] * B[K,N] (+bias). Dims multiples of tile.
// ---------------------------------------------------------------------------
__global__ __launch_bounds__(NTHREADS)
void gemm_nn_kernel(const float* __restrict__ A, const float* __restrict__ Bm,
                    float* __restrict__ C, const float* __restrict__ bias,
                    int K, int lda, int ldb, int ldc)
{
    __shared__ float As[BK][BM + 4];
    __shared__ float Bs[BK][BN + 4];

    const int bx = blockIdx.x;              // N block
    const int by = blockIdx.y;              // M block
    const int tid = threadIdx.x;
    const int tm = tid >> 4;                // 0..15
    const int tn = tid & 15;                // 0..15

    const float* Ab = A + (size_t)by * BM * lda;
    const float* Bb = Bm + (size_t)bx * BN;

    float acc[TM][TN];
    #pragma unroll
    for (int i = 0; i < TM; i++)
        #pragma unroll
        for (int j = 0; j < TN; j++) acc[i][j] = 0.f;

    for (int k0 = 0; k0 < K; k0 += BK) {
        #pragma unroll
        for (int r = 0; r < 2; r++) {                 // A tile: 128x16
            int id = tid * 2 + r;                     // 0..511
            int row = id >> 2;
            int c4 = (id & 3) * 4;
            float4 v = *(const float4*)(Ab + (size_t)row * lda + k0 + c4);
            As[c4 + 0][row] = v.x; As[c4 + 1][row] = v.y;
            As[c4 + 2][row] = v.z; As[c4 + 3][row] = v.w;
        }
        #pragma unroll
        for (int r = 0; r < 2; r++) {                 // B tile: 16x128
            int id = tid * 2 + r;
            int row = id >> 5;                        // 0..15
            int c4 = (id & 31) * 4;
            float4 v = *(const float4*)(Bb + (size_t)(k0 + row) * ldb + c4);
            *(float4*)&Bs[row][c4] = v;
        }
        __syncthreads();

        #pragma unroll
        for (int kk = 0; kk < BK; kk++) {
            float a[TM], b[TN];
            #pragma unroll
            for (int i = 0; i < TM; i++) a[i] = As[kk][tm * TM + i];
            #pragma unroll
            for (int j = 0; j < TN; j++) b[j] = Bs[kk][tn * TN + j];
            #pragma unroll
            for (int i = 0; i < TM; i++)
                #pragma unroll
                for (int j = 0; j < TN; j++)
                    acc[i][j] += a[i] * b[j];
        }
        __syncthreads();
    }

    float* Cb = C + (size_t)(by * BM + tm * TM) * ldc + bx * BN + tn * TN;
    #pragma unroll
    for (int i = 0; i < TM; i++) {
        #pragma unroll
        for (int j = 0; j < TN; j++) {
            float v = acc[i][j];
            if (bias) v += bias[bx * BN + tn * TN + j];
            Cb[(size_t)i * ldc + j] = v;
        }
    }
}

// ---------------------------------------------------------------------------
// QK^T (NT GEMM, causal block-skip): sim[b,i,j] = scale * dot(Q[b,i,:],K[b,j,:])
// grid: (S/BN, S/BM, B). Upper-triangular blocks skipped (never read later).
// ---------------------------------------------------------------------------
__global__ __launch_bounds__(NTHREADS)
void qk_kernel(const float* __restrict__ qkv, float* __restrict__ sim, float scale)
{
    const int bx = blockIdx.x;              // j block
    const int by = blockIdx.y;              // i block
    if (bx > by) return;                    // strictly upper block: unused
    const int bb = blockIdx.z;

    __shared__ float As[BK][BM + 4];
    __shared__ float Bs[BK][BN + 4];

    const int tid = threadIdx.x;
    const int tm = tid >> 4;
    const int tn = tid & 15;

    const float* Q = qkv + (size_t)bb * S_ * N1;           // col 0
    const float* Km = qkv + (size_t)bb * S_ * N1 + DINNER; // col 1024
    const float* Ab = Q + (size_t)by * BM * N1;
    const float* Bb = Km + (size_t)bx * BN * N1;

    float acc[TM][TN];
    #pragma unroll
    for (int i = 0; i < TM; i++)
        #pragma unroll
        for (int j = 0; j < TN; j++) acc[i][j] = 0.f;

    for (int k0 = 0; k0 < DINNER; k0 += BK) {
        #pragma unroll
        for (int r = 0; r < 2; r++) {
            int id = tid * 2 + r;
            int row = id >> 2;
            int c4 = (id & 3) * 4;
            float4 v = *(const float4*)(Ab + (size_t)row * N1 + k0 + c4);
            As[c4 + 0][row] = v.x; As[c4 + 1][row] = v.y;
            As[c4 + 2][row] = v.z; As[c4 + 3][row] = v.w;
        }
        #pragma unroll
        for (int r = 0; r < 2; r++) {                 // K rows (NT): same shape as A
            int id = tid * 2 + r;
            int row = id >> 2;
            int c4 = (id & 3) * 4;
            float4 v = *(const float4*)(Bb + (size_t)row * N1 + k0 + c4);
            Bs[c4 + 0][row] = v.x; Bs[c4 + 1][row] = v.y;
            Bs[c4 + 2][row] = v.z; Bs[c4 + 3][row] = v.w;
        }
        __syncthreads();

        #pragma unroll
        for (int kk = 0; kk < BK; kk++) {
            float a[TM], b[TN];
            #pragma unroll
            for (int i = 0; i < TM; i++) a[i] = As[kk][tm * TM + i];
            #pragma unroll
            for (int j = 0; j < TN; j++) b[j] = Bs[kk][tn * TN + j];
            #pragma unroll
            for (int i = 0; i < TM; i++)
                #pragma unroll
                for (int j = 0; j < TN; j++)
                    acc[i][j] += a[i] * b[j];
        }
        __syncthreads();
    }

    float* Cb = sim + (size_t)bb * S_ * S_
                    + (size_t)(by * BM + tm * TM) * S_ + bx * BN + tn * TN;
    #pragma unroll
    for (int i = 0; i < TM; i++)
        #pragma unroll
        for (int j = 0; j < TN; j++)
            Cb[(size_t)i * S_ + j] = acc[i][j] * scale;
}

// ---------------------------------------------------------------------------
// Causal row softmax, in place. Reads/writes only j<=i; zero-fills up to the
// end of the diagonal 128-block so PV can consume full tiles.
// grid: (S, B), block: 256
// ---------------------------------------------------------------------------
__global__ __launch_bounds__(256)
void softmax_kernel(float* __restrict__ sim)
{
    const int i = blockIdx.x;
    const int b = blockIdx.y;
    float* row = sim + ((size_t)b * S_ + i) * S_;
    const int n = i + 1;

    __shared__ float red[256];
    const int t = threadIdx.x;

    // row max
    float m = -FLT_MAX;
    for (int j = t; j < n; j += 256) m = fmaxf(m, row[j]);
    red[t] = m; __syncthreads();
    for (int s = 128; s > 0; s >>= 1) {
        if (t < s) red[t] = fmaxf(red[t], red[t + s]);
        __syncthreads();
    }
    m = red[0]; __syncthreads();

    // sum of exp
    float sum = 0.f;
    for (int j = t; j < n; j += 256) sum += expf(row[j] - m);
    red[t] = sum; __syncthreads();
    for (int s = 128; s > 0; s >>= 1) {
        if (t < s) red[t] += red[t + s];
        __syncthreads();
    }
    const float inv = 1.f / red[0];
    __syncthreads();

    // write probs
    for (int j = t; j < n; j += 256) row[j] = expf(row[j] - m) * inv;
    // zero-fill to end of diagonal block
    const int pad_end = min(S_, ((n + BM - 1) / BM) * BM);
    for (int j = n + t; j < pad_end; j += 256) row[j] = 0.f;
}

// ---------------------------------------------------------------------------
// PV: inner[b,i,:] = sum_j attn[b,i,j] * V[b,j,:], K-loop limited to causal
// reach of the row block. grid: (DINNER/BN, S/BM, B)
// ---------------------------------------------------------------------------
__global__ __launch_bounds__(NTHREADS)
void pv_kernel(const float* __restrict__ attn, const float* __restrict__ qkv,
               float* __restrict__ inner)
{
    const int bx = blockIdx.x;
    const int by = blockIdx.y;
    const int bb = blockIdx.z;

    __shared__ float As[BK][BM + 4];
    __shared__ float Bs[BK][BN + 4];

    const int tid = threadIdx.x;
    const int tm = tid >> 4;
    const int tn = tid & 15;

    const float* A = attn + (size_t)bb * S_ * S_;
    const float* V = qkv + (size_t)bb * S_ * N1 + 2 * DINNER;  // col 2048
    const float* Ab = A + (size_t)by * BM * S_;
    const float* Bb = V + (size_t)bx * BN;

    const int kmax = min(S_, by * BM + BM);   // causal reach (multiple of 128)

    float acc[TM][TN];
    #pragma unroll
    for (int i = 0; i < TM; i++)
        #pragma unroll
        for (int j = 0; j < TN; j++) acc[i][j] = 0.f;

    for (int k0 = 0; k0 < kmax; k0 += BK) {
        #pragma unroll
        for (int r = 0; r < 2; r++) {
            int id = tid * 2 + r;
            int row = id >> 2;
            int c4 = (id & 3) * 4;
            float4 v = *(const float4*)(Ab + (size_t)row * S_ + k0 + c4);
            As[c4 + 0][row] = v.x; As[c4 + 1][row] = v.y;
            As[c4 + 2][row] = v.z; As[c4 + 3][row] = v.w;
        }
        #pragma unroll
        for (int r = 0; r < 2; r++) {
            int id = tid * 2 + r;
            int row = id >> 5;
            int c4 = (id & 31) * 4;
            float4 v = *(const float4*)(Bb + (size_t)(k0 + row) * N1 + c4);
            *(float4*)&Bs[row][c4] = v;
        }
        __syncthreads();

        #pragma unroll
        for (int kk = 0; kk < BK; kk++) {
            float a[TM], b[TN];
            #pragma unroll
            for (int i = 0; i < TM; i++) a[i] = As[kk][tm * TM + i];
            #pragma unroll
            for (int j = 0; j < TN; j++) b[j] = Bs[kk][tn * TN + j];
            #pragma unroll
            for (int i = 0; i < TM; i++)
                #pragma unroll
                for (int j = 0; j < TN; j++)
                    acc[i][j] += a[i] * b[j];
        }
        __syncthreads();
    }

    float* Cb = inner + (size_t)bb * S_ * DINNER
                      + (size_t)(by * BM + tm * TM) * DINNER + bx * BN + tn * TN;
    #pragma unroll
    for (int i = 0; i < TM; i++)
        #pragma unroll
        for (int j = 0; j < TN; j++)
            Cb[(size_t)i * DINNER + j] = acc[i][j];
}

// ---------------------------------------------------------------------------
// Launch
// ---------------------------------------------------------------------------
extern "C" void kernel_launch(void* const* d_in, const int* in_sizes, int n_in,
                              void* d_out, int out_size)
{
    const float* x     = (const float*)d_in[0];   // [4,2048,1024]
    const float* w_qkv = (const float*)d_in[1];   // [1024,3072]
    const float* w_out = (const float*)d_in[2];   // [1024,1024]
    const float* b_out = (const float*)d_in[3];   // [1024]
    float* out = (float*)d_out;                   // [4,2048,1024]

    float* qkv;   cudaGetSymbolAddress((void**)&qkv,   g_qkv);
    float* sim;   cudaGetSymbolAddress((void**)&sim,   g_sim);
    float* inner; cudaGetSymbolAddress((void**)&inner, g_inner);

    const float scale = 1.0f / 32.0f;  // DIM_INNER^-0.5

    // 1) QKV projection: [8192,1024] @ [1024,3072]
    gemm_nn_kernel<<<dim3(N1 / BN, M1 / BM), NTHREADS>>>(
        x, w_qkv, qkv, nullptr, DIN, DIN, N1, N1);

    // 2) sim = scale * Q K^T (causal blocks only)
    qk_kernel<<<dim3(S_ / BN, S_ / BM, B_), NTHREADS>>>(qkv, sim, scale);

    // 3) causal softmax in place
    softmax_kernel<<<dim3(S_, B_), 256>>>(sim);

    // 4) inner = attn @ V (causal K-limit)
    pv_kernel<<<dim3(DINNER / BN, S_ / BM, B_), NTHREADS>>>(sim, qkv, inner);

    // 5) out = inner @ W_out + b_out
    gemm_nn_kernel<<<dim3(DOUT / BN, M1 / BM), NTHREADS>>>(
        inner, w_out, out, b_out, DINNER, DINNER, DOUT, DOUT);
}

// round 3
// speedup vs baseline: 2.1395x; 2.1395x over previous
#include <cuda_runtime.h>
#include <cuda_bf16.h>
#include <cstdint>
#include <float.h>

// ---------------------------------------------------------------------------
// Problem constants
// ---------------------------------------------------------------------------
#define B_     4
#define S_     2048
#define DIN    1024
#define DINNER 1024
#define DOUT   1024
#define M1     (B_ * S_)        // 8192
#define N1     (3 * DINNER)     // 3072

// GEMM tile config (mma.sync)
#define BM 128
#define BN 128
#define BK 32
#define NTH 256                 // 8 warps: 4 (m) x 2 (n)
#define PAD 8
#define LDSROW (BK + PAD)       // 40 bf16 per smem row (80 B)
#define TILE_B (BM * LDSROW * 2)    // 10240 bytes per tile
#define STAGE_B (4 * TILE_B)        // Ah, Al, Bh, Bl = 40960
#define SMEM_TOTAL (2 * STAGE_B)    // 81920

// ---------------------------------------------------------------------------
// PTX helpers (all baseline-PTX legal on compute_103)
// ---------------------------------------------------------------------------
__device__ __forceinline__ uint32_t smem_u32(const void* p) {
    uint32_t a;
    asm("{ .reg .u64 t; cvta.to.shared.u64 t, %1; cvt.u32.u64 %0, t; }"
        : "=r"(a) : "l"(p));
    return a;
}

__device__ __forceinline__ void cp_async16(uint32_t dst, const void* src) {
    asm volatile("cp.async.cg.shared.global [%0], [%1], 16;"
                 :: "r"(dst), "l"(src));
}
#define CP_COMMIT() asm volatile("cp.async.commit_group;" ::: "memory")
#define CP_WAIT(n)  asm volatile("cp.async.wait_group %0;" :: "n"(n) : "memory")

__device__ __forceinline__ void ldmat_x4(uint32_t& r0, uint32_t& r1,
                                         uint32_t& r2, uint32_t& r3,
                                         uint32_t addr) {
    asm volatile("ldmatrix.sync.aligned.m8n8.x4.shared.b16 {%0,%1,%2,%3}, [%4];"
                 : "=r"(r0), "=r"(r1), "=r"(r2), "=r"(r3) : "r"(addr));
}

__device__ __forceinline__ void mma_bf16(float* c, const uint32_t* a,
                                         uint32_t b0, uint32_t b1) {
    asm volatile(
        "mma.sync.aligned.m16n8k16.row.col.f32.bf16.bf16.f32 "
        "{%0,%1,%2,%3}, {%4,%5,%6,%7}, {%8,%9}, {%0,%1,%2,%3};"
        : "+f"(c[0]), "+f"(c[1]), "+f"(c[2]), "+f"(c[3])
        : "r"(a[0]), "r"(a[1]), "r"(a[2]), "r"(a[3]), "r"(b0), "r"(b1));
}

// ---------------------------------------------------------------------------
// Scratch (static device globals)
// ---------------------------------------------------------------------------
__device__ float g_qkv[(size_t)M1 * N1];                     // 96 MB fp32
__device__ float g_sim[(size_t)B_ * S_ * S_];                // 64 MB fp32

__device__ __nv_bfloat16 g_xh[(size_t)M1 * DIN];
__device__ __nv_bfloat16 g_xl[(size_t)M1 * DIN];
__device__ __nv_bfloat16 g_wqkvt_h[(size_t)N1 * DIN];
__device__ __nv_bfloat16 g_wqkvt_l[(size_t)N1 * DIN];
__device__ __nv_bfloat16 g_woutt_h[(size_t)DOUT * DINNER];
__device__ __nv_bfloat16 g_woutt_l[(size_t)DOUT * DINNER];
__device__ __nv_bfloat16 g_qkvh[(size_t)M1 * N1];
__device__ __nv_bfloat16 g_qkvl[(size_t)M1 * N1];
__device__ __nv_bfloat16 g_vth[(size_t)B_ * DINNER * S_];    // V^T per batch
__device__ __nv_bfloat16 g_vtl[(size_t)B_ * DINNER * S_];
__device__ __nv_bfloat16 g_attnh[(size_t)B_ * S_ * S_];
__device__ __nv_bfloat16 g_attnl[(size_t)B_ * S_ * S_];
__device__ __nv_bfloat16 g_innerh[(size_t)M1 * DINNER];
__device__ __nv_bfloat16 g_innerl[(size_t)M1 * DINNER];

// ---------------------------------------------------------------------------
// hi/lo split helpers + conversion kernels
// ---------------------------------------------------------------------------
__device__ __forceinline__ void split2(float x, __nv_bfloat16& h, __nv_bfloat16& l) {
    h = __float2bfloat16(x);
    l = __float2bfloat16(x - __bfloat162float(h));
}

__global__ void cvt_rm_kernel(const float4* __restrict__ src,
                              __nv_bfloat162* __restrict__ h,
                              __nv_bfloat162* __restrict__ l, long long n4) {
    long long i = (long long)blockIdx.x * blockDim.x + threadIdx.x;
    long long stride = (long long)gridDim.x * blockDim.x;
    for (; i < n4; i += stride) {
        float4 v = src[i];
        __nv_bfloat16 h0, h1, h2, h3, l0, l1, l2, l3;
        split2(v.x, h0, l0); split2(v.y, h1, l1);
        split2(v.z, h2, l2); split2(v.w, h3, l3);
        h[2 * i]     = __halves2bfloat162(h0, h1);
        h[2 * i + 1] = __halves2bfloat162(h2, h3);
        l[2 * i]     = __halves2bfloat162(l0, l1);
        l[2 * i + 1] = __halves2bfloat162(l2, l3);
    }
}

// fp32 [R,C] (row stride sld) -> transposed bf16 hi/lo [C,R] (row stride dld)
__global__ void cvt_tr_kernel(const float* __restrict__ src,
                              __nv_bfloat16* __restrict__ h,
                              __nv_bfloat16* __restrict__ l,
                              int sld, int dld,
                              long long sbatch, long long dbatch) {
    __shared__ float t[32][33];
    const int c0 = blockIdx.x * 32;
    const int r0 = blockIdx.y * 32;
    const long long sb = (long long)blockIdx.z * sbatch;
    const long long db = (long long)blockIdx.z * dbatch;
    const int tx = threadIdx.x, ty = threadIdx.y;

    #pragma unroll
    for (int i = 0; i < 32; i += 8)
        t[ty + i][tx] = src[sb + (long long)(r0 + ty + i) * sld + c0 + tx];
    __syncthreads();
    #pragma unroll
    for (int i = 0; i < 32; i += 8) {
        float v = t[tx][ty + i];
        __nv_bfloat16 hh, ll;
        split2(v, hh, ll);
        long long o = db + (long long)(c0 + ty + i) * dld + r0 + tx;
        h[o] = hh;
        l[o] = ll;
    }
}

// ---------------------------------------------------------------------------
// mma.sync bf16 split GEMM: C[M,N] = scale * sum_k A[m,k]*B[n,k] (+bias)
// A: [M,K] K-contiguous ; B: [N,K] K-contiguous
// ---------------------------------------------------------------------------
struct GemmArgs {
    const __nv_bfloat16 *Ah, *Al, *Bh, *Bl;
    float* C;                    // nullable
    __nv_bfloat16 *Ch, *Cl;      // nullable: bf16 hi/lo outputs
    const float* bias;           // nullable
    int K, lda, ldb, ldc;
    long long strideA, strideB, strideC;
    float scale;
    int causal_skip;             // skip CTA if bx > by
    int kmax_mode;               // K_eff = min(K, (by+1)*BM)
};

__device__ __forceinline__ void load_tile(const __nv_bfloat16* __restrict__ g,
                                          int row0, int ld, int k0, uint32_t sm) {
    const int tid = threadIdx.x;
    #pragma unroll
    for (int t = 0; t < 2; t++) {
        int idx = t * NTH + tid;        // 0..511
        int r  = idx >> 2;              // 0..127
        int kc = (idx & 3) * 8;         // 0,8,16,24
        cp_async16(sm + (uint32_t)(r * LDSROW + kc) * 2,
                   g + (long long)(row0 + r) * ld + k0 + kc);
    }
}

__global__ void __launch_bounds__(NTH, 1)
gemm_mma_kernel(GemmArgs args)
{
    const int bx = blockIdx.x, by = blockIdx.y, bb = blockIdx.z;
    if (args.causal_skip && bx > by) return;

    extern __shared__ char smem[];
    const uint32_t smem_base = smem_u32(smem);

    const int tid = threadIdx.x;
    const int wid = tid >> 5;
    const int lane = tid & 31;
    const int wm = wid >> 1;            // 0..3  (32-row slab)
    const int wn = wid & 1;             // 0..1  (64-col slab)
    const int lrow = lane & 15;         // ldmatrix row select
    const int lcol = (lane >> 4) * 8;   // ldmatrix k-half select

    const __nv_bfloat16* Ah = args.Ah + (long long)bb * args.strideA;
    const __nv_bfloat16* Al = args.Al + (long long)bb * args.strideA;
    const __nv_bfloat16* Bh = args.Bh + (long long)bb * args.strideB;
    const __nv_bfloat16* Bl = args.Bl + (long long)bb * args.strideB;

    const int Keff = args.kmax_mode ? min(args.K, (by + 1) * BM) : args.K;
    const int nch = Keff / BK;
    const int arow = by * BM;
    const int brow = bx * BN;

    float acc[2][8][4];
    #pragma unroll
    for (int i = 0; i < 2; i++)
        #pragma unroll
        for (int j = 0; j < 8; j++)
            #pragma unroll
            for (int k = 0; k < 4; k++) acc[i][j][k] = 0.f;

    // prologue: chunk 0 -> stage 0
    load_tile(Ah, arow, args.lda, 0, smem_base);
    load_tile(Al, arow, args.lda, 0, smem_base + TILE_B);
    load_tile(Bh, brow, args.ldb, 0, smem_base + 2 * TILE_B);
    load_tile(Bl, brow, args.ldb, 0, smem_base + 3 * TILE_B);
    CP_COMMIT();

    for (int c = 0; c < nch; c++) {
        const int p = c & 1;
        if (c + 1 < nch) {
            const uint32_t sq = smem_base + (p ^ 1) * STAGE_B;
            const int k0 = (c + 1) * BK;
            load_tile(Ah, arow, args.lda, k0, sq);
            load_tile(Al, arow, args.lda, k0, sq + TILE_B);
            load_tile(Bh, brow, args.ldb, k0, sq + 2 * TILE_B);
            load_tile(Bl, brow, args.ldb, k0, sq + 3 * TILE_B);
            CP_COMMIT();
            CP_WAIT(1);
        } else {
            CP_WAIT(0);
        }
        __syncthreads();

        const uint32_t sp = smem_base + p * STAGE_B;
        #pragma unroll
        for (int kk = 0; kk < 2; kk++) {
            const uint32_t koff = (uint32_t)(kk * 16 + lcol) * 2;
            // A fragments (hi, lo), 2 m16 blocks
            uint32_t ah[2][4], al[2][4];
            #pragma unroll
            for (int mi = 0; mi < 2; mi++) {
                uint32_t ra = (uint32_t)((wm * 32 + mi * 16 + lrow) * LDSROW) * 2 + koff;
                ldmat_x4(ah[mi][0], ah[mi][1], ah[mi][2], ah[mi][3], sp + ra);
                ldmat_x4(al[mi][0], al[mi][1], al[mi][2], al[mi][3], sp + TILE_B + ra);
            }
            // B fragments (hi, lo), 8 n8 blocks
            uint32_t bh0[8], bh1[8], bl0[8], bl1[8];
            #pragma unroll
            for (int np = 0; np < 4; np++) {
                uint32_t rb = (uint32_t)((wn * 64 + np * 16 + lrow) * LDSROW) * 2 + koff;
                uint32_t r0, r1, r2, r3;
                ldmat_x4(r0, r1, r2, r3, sp + 2 * TILE_B + rb);
                bh0[np * 2] = r0; bh1[np * 2] = r2;
                bh0[np * 2 + 1] = r1; bh1[np * 2 + 1] = r3;
                ldmat_x4(r0, r1, r2, r3, sp + 3 * TILE_B + rb);
                bl0[np * 2] = r0; bl1[np * 2] = r2;
                bl0[np * 2 + 1] = r1; bl1[np * 2 + 1] = r3;
            }
            // 3-pass MMAs
            #pragma unroll
            for (int mi = 0; mi < 2; mi++)
                #pragma unroll
                for (int j = 0; j < 8; j++) {
                    mma_bf16(acc[mi][j], ah[mi], bh0[j], bh1[j]);
                    mma_bf16(acc[mi][j], ah[mi], bl0[j], bl1[j]);
                    mma_bf16(acc[mi][j], al[mi], bh0[j], bh1[j]);
                }
        }
        __syncthreads();
    }

    // epilogue
    float* C = args.C ? args.C + (long long)bb * args.strideC : nullptr;
    __nv_bfloat16* Ch = args.Ch ? args.Ch + (long long)bb * args.strideC : nullptr;
    __nv_bfloat16* Cl = args.Cl ? args.Cl + (long long)bb * args.strideC : nullptr;
    const int g = lane >> 2;
    const int tig = lane & 3;

    #pragma unroll
    for (int mi = 0; mi < 2; mi++) {
        #pragma unroll
        for (int j = 0; j < 8; j++) {
            const int row0 = arow + wm * 32 + mi * 16 + g;
            const int col0 = brow + wn * 64 + j * 8 + 2 * tig;
            float v[4];
            #pragma unroll
            for (int k = 0; k < 4; k++) v[k] = acc[mi][j][k] * args.scale;
            if (args.bias) {
                v[0] += args.bias[col0];     v[1] += args.bias[col0 + 1];
                v[2] += args.bias[col0];     v[3] += args.bias[col0 + 1];
            }
            const long long o0 = (long long)row0 * args.ldc + col0;
            const long long o1 = (long long)(row0 + 8) * args.ldc + col0;
            if (C) {
                C[o0] = v[0]; C[o0 + 1] = v[1];
                C[o1] = v[2]; C[o1 + 1] = v[3];
            }
            if (Ch) {
                __nv_bfloat16 h0, h1, h2, h3, l0, l1, l2, l3;
                split2(v[0], h0, l0); split2(v[1], h1, l1);
                split2(v[2], h2, l2); split2(v[3], h3, l3);
                *(__nv_bfloat162*)(Ch + o0) = __halves2bfloat162(h0, h1);
                *(__nv_bfloat162*)(Ch + o1) = __halves2bfloat162(h2, h3);
                *(__nv_bfloat162*)(Cl + o0) = __halves2bfloat162(l0, l1);
                *(__nv_bfloat162*)(Cl + o1) = __halves2bfloat162(l2, l3);
            }
        }
    }
}

// ---------------------------------------------------------------------------
// Causal row softmax: fp32 sim -> bf16 hi/lo probs, zero-filled to 128 edge
// ---------------------------------------------------------------------------
__global__ void __launch_bounds__(256)
softmax_kernel(const float* __restrict__ sim,
               __nv_bfloat16* __restrict__ ph, __nv_bfloat16* __restrict__ pl)
{
    const int i = blockIdx.x;
    const int b = blockIdx.y;
    const float* row = sim + ((size_t)b * S_ + i) * S_;
    __nv_bfloat16* rh = ph + ((size_t)b * S_ + i) * S_;
    __nv_bfloat16* rl = pl + ((size_t)b * S_ + i) * S_;
    const int n = i + 1;

    __shared__ float red[256];
    const int t = threadIdx.x;

    float m = -FLT_MAX;
    for (int j = t; j < n; j += 256) m = fmaxf(m, row[j]);
    red[t] = m; __syncthreads();
    for (int s = 128; s > 0; s >>= 1) {
        if (t < s) red[t] = fmaxf(red[t], red[t + s]);
        __syncthreads();
    }
    m = red[0]; __syncthreads();

    float sum = 0.f;
    for (int j = t; j < n; j += 256) sum += expf(row[j] - m);
    red[t] = sum; __syncthreads();
    for (int s = 128; s > 0; s >>= 1) {
        if (t < s) red[t] += red[t + s];
        __syncthreads();
    }
    const float inv = 1.f / red[0];
    __syncthreads();

    for (int j = t; j < n; j += 256) {
        float p = expf(row[j] - m) * inv;
        __nv_bfloat16 h, l;
        split2(p, h, l);
        rh[j] = h; rl[j] = l;
    }
    const int pad_end = min(S_, ((n + BM - 1) / BM) * BM);
    for (int j = n + t; j < pad_end; j += 256) {
        rh[j] = __float2bfloat16(0.f);
        rl[j] = __float2bfloat16(0.f);
    }
}

// ---------------------------------------------------------------------------
// Launch
// ---------------------------------------------------------------------------
static void* sym(const void* s) { void* p; cudaGetSymbolAddress(&p, s); return p; }

extern "C" void kernel_launch(void* const* d_in, const int* in_sizes, int n_in,
                              void* d_out, int out_size)
{
    const float* x     = (const float*)d_in[0];
    const float* w_qkv = (const float*)d_in[1];
    const float* w_out = (const float*)d_in[2];
    const float* b_out = (const float*)d_in[3];
    float* out = (float*)d_out;

    float* qkv  = (float*)sym(g_qkv);
    float* simP = (float*)sym(g_sim);
    __nv_bfloat16* xh = (__nv_bfloat16*)sym(g_xh);
    __nv_bfloat16* xl = (__nv_bfloat16*)sym(g_xl);
    __nv_bfloat16* wqt_h = (__nv_bfloat16*)sym(g_wqkvt_h);
    __nv_bfloat16* wqt_l = (__nv_bfloat16*)sym(g_wqkvt_l);
    __nv_bfloat16* wot_h = (__nv_bfloat16*)sym(g_woutt_h);
    __nv_bfloat16* wot_l = (__nv_bfloat16*)sym(g_woutt_l);
    __nv_bfloat16* qkvh = (__nv_bfloat16*)sym(g_qkvh);
    __nv_bfloat16* qkvl = (__nv_bfloat16*)sym(g_qkvl);
    __nv_bfloat16* vth = (__nv_bfloat16*)sym(g_vth);
    __nv_bfloat16* vtl = (__nv_bfloat16*)sym(g_vtl);
    __nv_bfloat16* ath = (__nv_bfloat16*)sym(g_attnh);
    __nv_bfloat16* atl = (__nv_bfloat16*)sym(g_attnl);
    __nv_bfloat16* inh = (__nv_bfloat16*)sym(g_innerh);
    __nv_bfloat16* inl = (__nv_bfloat16*)sym(g_innerl);

    cudaFuncSetAttribute(gemm_mma_kernel,
                         cudaFuncAttributeMaxDynamicSharedMemorySize, SMEM_TOTAL);

    const float scale = 1.0f / 32.0f;   // DIM_INNER^-0.5

    // 1) input splits / weight transposes
    cvt_rm_kernel<<<2048, 256>>>((const float4*)x, (__nv_bfloat162*)xh,
                                 (__nv_bfloat162*)xl, (long long)M1 * DIN / 4);
    cvt_tr_kernel<<<dim3(N1 / 32, DIN / 32, 1), dim3(32, 8)>>>(
        w_qkv, wqt_h, wqt_l, N1, DIN, 0, 0);
    cvt_tr_kernel<<<dim3(DOUT / 32, DINNER / 32, 1), dim3(32, 8)>>>(
        w_out, wot_h, wot_l, DOUT, DINNER, 0, 0);

    // 2) QKV projection -> fp32 qkv + bf16 split (fused)
    {
        GemmArgs a = { xh, xl, wqt_h, wqt_l, qkv, qkvh, qkvl, nullptr,
                       DIN, DIN, DIN, N1, 0, 0, 0, 1.0f, 0, 0 };
        gemm_mma_kernel<<<dim3(N1 / BN, M1 / BM, 1), NTH, SMEM_TOTAL>>>(a);
    }

    // 3) V transpose+split (per batch)
    cvt_tr_kernel<<<dim3(DINNER / 32, S_ / 32, B_), dim3(32, 8)>>>(
        qkv + 2 * DINNER, vth, vtl, N1, S_,
        (long long)S_ * N1, (long long)DINNER * S_);

    // 4) sim = scale * Q K^T (causal blocks only), fp32
    {
        GemmArgs a = { qkvh, qkvl, qkvh + DINNER, qkvl + DINNER, simP,
                       nullptr, nullptr, nullptr,
                       DINNER, N1, N1, S_,
                       (long long)S_ * N1, (long long)S_ * N1, (long long)S_ * S_,
                       scale, 1, 0 };
        gemm_mma_kernel<<<dim3(S_ / BN, S_ / BM, B_), NTH, SMEM_TOTAL>>>(a);
    }

    // 5) softmax -> bf16 split probs (fused)
    softmax_kernel<<<dim3(S_, B_), 256>>>(simP, ath, atl);

    // 6) inner = attn @ V -> bf16 split only (fused, causal K-limit)
    {
        GemmArgs a = { ath, atl, vth, vtl, nullptr, inh, inl, nullptr,
                       S_, S_, S_, DINNER,
                       (long long)S_ * S_, (long long)DINNER * S_,
                       (long long)S_ * DINNER,
                       1.0f, 0, 1 };
        gemm_mma_kernel<<<dim3(DINNER / BN, S_ / BM, B_), NTH, SMEM_TOTAL>>>(a);
    }

    // 7) out = inner @ W_out + b_out (fp32)
    {
        GemmArgs a = { inh, inl, wot_h, wot_l, out, nullptr, nullptr, b_out,
                       DINNER, DINNER, DINNER, DOUT, 0, 0, 0, 1.0f, 0, 0 };
        gemm_mma_kernel<<<dim3(DOUT / BN, M1 / BM, 1), NTH, SMEM_TOTAL>>>(a);
    }
}

// round 4
// speedup vs baseline: 2.3223x; 1.0854x over previous
#include <cuda_runtime.h>
#include <cuda_bf16.h>
#include <cstdint>
#include <float.h>

// ---------------------------------------------------------------------------
// Problem constants
// ---------------------------------------------------------------------------
#define B_     4
#define S_     2048
#define DIN    1024
#define DINNER 1024
#define DOUT   1024
#define M1     (B_ * S_)        // 8192
#define N1     (3 * DINNER)     // 3072

// GEMM tile config (mma.sync)
#define BM 128
#define BN 128
#define BK 32
#define NTH 256                 // 8 warps: 4 (m) x 2 (n)
#define PAD 8
#define LDSROW (BK + PAD)       // 40 bf16 per smem row (80 B)
#define TILE_B (BM * LDSROW * 2)    // 10240 bytes per tile
#define STAGE_B (4 * TILE_B)        // Ah, Al, Bh, Bl = 40960
#define SMEM_TOTAL (2 * STAGE_B)    // 81920

// ---------------------------------------------------------------------------
// PTX helpers (all baseline-PTX legal on compute_103)
// ---------------------------------------------------------------------------
__device__ __forceinline__ uint32_t smem_u32(const void* p) {
    uint32_t a;
    asm("{ .reg .u64 t; cvta.to.shared.u64 t, %1; cvt.u32.u64 %0, t; }"
        : "=r"(a) : "l"(p));
    return a;
}

__device__ __forceinline__ void cp_async16(uint32_t dst, const void* src) {
    asm volatile("cp.async.cg.shared.global [%0], [%1], 16;"
                 :: "r"(dst), "l"(src));
}
#define CP_COMMIT() asm volatile("cp.async.commit_group;" ::: "memory")
#define CP_WAIT(n)  asm volatile("cp.async.wait_group %0;" :: "n"(n) : "memory")

__device__ __forceinline__ void ldmat_x4(uint32_t& r0, uint32_t& r1,
                                         uint32_t& r2, uint32_t& r3,
                                         uint32_t addr) {
    asm volatile("ldmatrix.sync.aligned.m8n8.x4.shared.b16 {%0,%1,%2,%3}, [%4];"
                 : "=r"(r0), "=r"(r1), "=r"(r2), "=r"(r3) : "r"(addr));
}

__device__ __forceinline__ void mma_bf16(float* c, const uint32_t* a,
                                         uint32_t b0, uint32_t b1) {
    asm volatile(
        "mma.sync.aligned.m16n8k16.row.col.f32.bf16.bf16.f32 "
        "{%0,%1,%2,%3}, {%4,%5,%6,%7}, {%8,%9}, {%0,%1,%2,%3};"
        : "+f"(c[0]), "+f"(c[1]), "+f"(c[2]), "+f"(c[3])
        : "r"(a[0]), "r"(a[1]), "r"(a[2]), "r"(a[3]), "r"(b0), "r"(b1));
}

// ---------------------------------------------------------------------------
// Scratch (static device globals)
// ---------------------------------------------------------------------------
__device__ float g_qkv[(size_t)M1 * N1];                     // 96 MB fp32
__device__ float g_sim[(size_t)B_ * S_ * S_];                // 64 MB fp32

__device__ __nv_bfloat16 g_xh[(size_t)M1 * DIN];
__device__ __nv_bfloat16 g_xl[(size_t)M1 * DIN];
__device__ __nv_bfloat16 g_wqkvt_h[(size_t)N1 * DIN];
__device__ __nv_bfloat16 g_wqkvt_l[(size_t)N1 * DIN];
__device__ __nv_bfloat16 g_woutt_h[(size_t)DOUT * DINNER];
__device__ __nv_bfloat16 g_woutt_l[(size_t)DOUT * DINNER];
__device__ __nv_bfloat16 g_qkvh[(size_t)M1 * N1];
__device__ __nv_bfloat16 g_qkvl[(size_t)M1 * N1];
__device__ __nv_bfloat16 g_vth[(size_t)B_ * DINNER * S_];    // V^T per batch
__device__ __nv_bfloat16 g_vtl[(size_t)B_ * DINNER * S_];
__device__ __nv_bfloat16 g_attnh[(size_t)B_ * S_ * S_];
__device__ __nv_bfloat16 g_attnl[(size_t)B_ * S_ * S_];
__device__ __nv_bfloat16 g_innerh[(size_t)M1 * DINNER];
__device__ __nv_bfloat16 g_innerl[(size_t)M1 * DINNER];

// ---------------------------------------------------------------------------
// hi/lo split helpers + conversion kernels
// ---------------------------------------------------------------------------
__device__ __forceinline__ void split2(float x, __nv_bfloat16& h, __nv_bfloat16& l) {
    h = __float2bfloat16(x);
    l = __float2bfloat16(x - __bfloat162float(h));
}

__global__ void cvt_rm_kernel(const float4* __restrict__ src,
                              __nv_bfloat162* __restrict__ h,
                              __nv_bfloat162* __restrict__ l, long long n4) {
    long long i = (long long)blockIdx.x * blockDim.x + threadIdx.x;
    long long stride = (long long)gridDim.x * blockDim.x;
    for (; i < n4; i += stride) {
        float4 v = src[i];
        __nv_bfloat16 h0, h1, h2, h3, l0, l1, l2, l3;
        split2(v.x, h0, l0); split2(v.y, h1, l1);
        split2(v.z, h2, l2); split2(v.w, h3, l3);
        h[2 * i]     = __halves2bfloat162(h0, h1);
        h[2 * i + 1] = __halves2bfloat162(h2, h3);
        l[2 * i]     = __halves2bfloat162(l0, l1);
        l[2 * i + 1] = __halves2bfloat162(l2, l3);
    }
}

// fp32 [R,C] (row stride sld) -> transposed bf16 hi/lo [C,R] (row stride dld)
__global__ void cvt_tr_kernel(const float* __restrict__ src,
                              __nv_bfloat16* __restrict__ h,
                              __nv_bfloat16* __restrict__ l,
                              int sld, int dld,
                              long long sbatch, long long dbatch) {
    __shared__ float t[32][33];
    const int c0 = blockIdx.x * 32;
    const int r0 = blockIdx.y * 32;
    const long long sb = (long long)blockIdx.z * sbatch;
    const long long db = (long long)blockIdx.z * dbatch;
    const int tx = threadIdx.x, ty = threadIdx.y;

    #pragma unroll
    for (int i = 0; i < 32; i += 8)
        t[ty + i][tx] = src[sb + (long long)(r0 + ty + i) * sld + c0 + tx];
    __syncthreads();
    #pragma unroll
    for (int i = 0; i < 32; i += 8) {
        float v = t[tx][ty + i];
        __nv_bfloat16 hh, ll;
        split2(v, hh, ll);
        long long o = db + (long long)(c0 + ty + i) * dld + r0 + tx;
        h[o] = hh;
        l[o] = ll;
    }
}

// ---------------------------------------------------------------------------
// mma.sync bf16 split GEMM: C[M,N] = scale * sum_k A[m,k]*B[n,k] (+bias)
// A: [M,K] K-contiguous ; B: [N,K] K-contiguous
// ---------------------------------------------------------------------------
struct GemmArgs {
    const __nv_bfloat16 *Ah, *Al, *Bh, *Bl;
    float* C;                    // nullable
    __nv_bfloat16 *Ch, *Cl;      // nullable: bf16 hi/lo outputs
    const float* bias;           // nullable
    int K, lda, ldb, ldc;
    long long strideA, strideB, strideC;
    float scale;
    int causal_skip;             // skip CTA if bx > by
    int kmax_mode;               // K_eff = min(K, (by+1)*BM)
};

__device__ __forceinline__ void load_tile(const __nv_bfloat16* __restrict__ g,
                                          int row0, int ld, int k0, uint32_t sm) {
    const int tid = threadIdx.x;
    #pragma unroll
    for (int t = 0; t < 2; t++) {
        int idx = t * NTH + tid;        // 0..511
        int r  = idx >> 2;              // 0..127
        int kc = (idx & 3) * 8;         // 0,8,16,24
        cp_async16(sm + (uint32_t)(r * LDSROW + kc) * 2,
                   g + (long long)(row0 + r) * ld + k0 + kc);
    }
}

__global__ void __launch_bounds__(NTH, 2)
gemm_mma_kernel(GemmArgs args)
{
    const int bx = blockIdx.x, by = blockIdx.y, bb = blockIdx.z;
    if (args.causal_skip && bx > by) return;

    extern __shared__ char smem[];
    const uint32_t smem_base = smem_u32(smem);

    const int tid = threadIdx.x;
    const int wid = tid >> 5;
    const int lane = tid & 31;
    const int wm = wid >> 1;            // 0..3  (32-row slab)
    const int wn = wid & 1;             // 0..1  (64-col slab)
    const int lrow = lane & 15;         // ldmatrix row select
    const int lcol = (lane >> 4) * 8;   // ldmatrix k-half select

    const __nv_bfloat16* Ah = args.Ah + (long long)bb * args.strideA;
    const __nv_bfloat16* Al = args.Al + (long long)bb * args.strideA;
    const __nv_bfloat16* Bh = args.Bh + (long long)bb * args.strideB;
    const __nv_bfloat16* Bl = args.Bl + (long long)bb * args.strideB;

    const int Keff = args.kmax_mode ? min(args.K, (by + 1) * BM) : args.K;
    const int nch = Keff / BK;
    const int arow = by * BM;
    const int brow = bx * BN;

    float acc[2][8][4];
    #pragma unroll
    for (int i = 0; i < 2; i++)
        #pragma unroll
        for (int j = 0; j < 8; j++)
            #pragma unroll
            for (int k = 0; k < 4; k++) acc[i][j][k] = 0.f;

    // prologue: chunk 0 -> stage 0
    load_tile(Ah, arow, args.lda, 0, smem_base);
    load_tile(Al, arow, args.lda, 0, smem_base + TILE_B);
    load_tile(Bh, brow, args.ldb, 0, smem_base + 2 * TILE_B);
    load_tile(Bl, brow, args.ldb, 0, smem_base + 3 * TILE_B);
    CP_COMMIT();

    for (int c = 0; c < nch; c++) {
        const int p = c & 1;
        if (c + 1 < nch) {
            const uint32_t sq = smem_base + (p ^ 1) * STAGE_B;
            const int k0 = (c + 1) * BK;
            load_tile(Ah, arow, args.lda, k0, sq);
            load_tile(Al, arow, args.lda, k0, sq + TILE_B);
            load_tile(Bh, brow, args.ldb, k0, sq + 2 * TILE_B);
            load_tile(Bl, brow, args.ldb, k0, sq + 3 * TILE_B);
            CP_COMMIT();
            CP_WAIT(1);
        } else {
            CP_WAIT(0);
        }
        __syncthreads();

        const uint32_t sp = smem_base + p * STAGE_B;
        #pragma unroll
        for (int kk = 0; kk < 2; kk++) {
            const uint32_t koff = (uint32_t)(kk * 16 + lcol) * 2;
            // A fragments (hi, lo), 2 m16 blocks — live across both j-groups
            uint32_t ah[2][4], al[2][4];
            #pragma unroll
            for (int mi = 0; mi < 2; mi++) {
                uint32_t ra = (uint32_t)((wm * 32 + mi * 16 + lrow) * LDSROW) * 2 + koff;
                ldmat_x4(ah[mi][0], ah[mi][1], ah[mi][2], ah[mi][3], sp + ra);
                ldmat_x4(al[mi][0], al[mi][1], al[mi][2], al[mi][3], sp + TILE_B + ra);
            }
            // B fragments processed in 2 groups of 4 j-blocks (halves live regs)
            #pragma unroll
            for (int jg = 0; jg < 2; jg++) {
                uint32_t bh0[4], bh1[4], bl0[4], bl1[4];
                #pragma unroll
                for (int np = 0; np < 2; np++) {
                    uint32_t rb = (uint32_t)((wn * 64 + (jg * 2 + np) * 16 + lrow)
                                             * LDSROW) * 2 + koff;
                    uint32_t r0, r1, r2, r3;
                    ldmat_x4(r0, r1, r2, r3, sp + 2 * TILE_B + rb);
                    bh0[np * 2] = r0; bh1[np * 2] = r2;
                    bh0[np * 2 + 1] = r1; bh1[np * 2 + 1] = r3;
                    ldmat_x4(r0, r1, r2, r3, sp + 3 * TILE_B + rb);
                    bl0[np * 2] = r0; bl1[np * 2] = r2;
                    bl0[np * 2 + 1] = r1; bl1[np * 2 + 1] = r3;
                }
                #pragma unroll
                for (int mi = 0; mi < 2; mi++)
                    #pragma unroll
                    for (int j = 0; j < 4; j++) {
                        float* a = acc[mi][jg * 4 + j];
                        mma_bf16(a, ah[mi], bh0[j], bh1[j]);
                        mma_bf16(a, ah[mi], bl0[j], bl1[j]);
                        mma_bf16(a, al[mi], bh0[j], bh1[j]);
                    }
            }
        }
        __syncthreads();
    }

    // epilogue
    float* C = args.C ? args.C + (long long)bb * args.strideC : nullptr;
    __nv_bfloat16* Ch = args.Ch ? args.Ch + (long long)bb * args.strideC : nullptr;
    __nv_bfloat16* Cl = args.Cl ? args.Cl + (long long)bb * args.strideC : nullptr;
    const int g = lane >> 2;
    const int tig = lane & 3;

    #pragma unroll
    for (int mi = 0; mi < 2; mi++) {
        #pragma unroll
        for (int j = 0; j < 8; j++) {
            const int row0 = arow + wm * 32 + mi * 16 + g;
            const int col0 = brow + wn * 64 + j * 8 + 2 * tig;
            float v[4];
            #pragma unroll
            for (int k = 0; k < 4; k++) v[k] = acc[mi][j][k] * args.scale;
            if (args.bias) {
                v[0] += args.bias[col0];     v[1] += args.bias[col0 + 1];
                v[2] += args.bias[col0];     v[3] += args.bias[col0 + 1];
            }
            const long long o0 = (long long)row0 * args.ldc + col0;
            const long long o1 = (long long)(row0 + 8) * args.ldc + col0;
            if (C) {
                C[o0] = v[0]; C[o0 + 1] = v[1];
                C[o1] = v[2]; C[o1 + 1] = v[3];
            }
            if (Ch) {
                __nv_bfloat16 h0, h1, h2, h3, l0, l1, l2, l3;
                split2(v[0], h0, l0); split2(v[1], h1, l1);
                split2(v[2], h2, l2); split2(v[3], h3, l3);
                *(__nv_bfloat162*)(Ch + o0) = __halves2bfloat162(h0, h1);
                *(__nv_bfloat162*)(Ch + o1) = __halves2bfloat162(h2, h3);
                *(__nv_bfloat162*)(Cl + o0) = __halves2bfloat162(l0, l1);
                *(__nv_bfloat162*)(Cl + o1) = __halves2bfloat162(l2, l3);
            }
        }
    }
}

// ---------------------------------------------------------------------------
// Causal row softmax: fp32 sim -> bf16 hi/lo probs, zero-filled to 128 edge
// ---------------------------------------------------------------------------
__global__ void __launch_bounds__(256)
softmax_kernel(const float* __restrict__ sim,
               __nv_bfloat16* __restrict__ ph, __nv_bfloat16* __restrict__ pl)
{
    const int i = blockIdx.x;
    const int b = blockIdx.y;
    const float* row = sim + ((size_t)b * S_ + i) * S_;
    __nv_bfloat16* rh = ph + ((size_t)b * S_ + i) * S_;
    __nv_bfloat16* rl = pl + ((size_t)b * S_ + i) * S_;
    const int n = i + 1;

    __shared__ float red[256];
    const int t = threadIdx.x;

    float m = -FLT_MAX;
    for (int j = t; j < n; j += 256) m = fmaxf(m, row[j]);
    red[t] = m; __syncthreads();
    for (int s = 128; s > 0; s >>= 1) {
        if (t < s) red[t] = fmaxf(red[t], red[t + s]);
        __syncthreads();
    }
    m = red[0]; __syncthreads();

    float sum = 0.f;
    for (int j = t; j < n; j += 256) sum += expf(row[j] - m);
    red[t] = sum; __syncthreads();
    for (int s = 128; s > 0; s >>= 1) {
        if (t < s) red[t] += red[t + s];
        __syncthreads();
    }
    const float inv = 1.f / red[0];
    __syncthreads();

    for (int j = t; j < n; j += 256) {
        float p = expf(row[j] - m) * inv;
        __nv_bfloat16 h, l;
        split2(p, h, l);
        rh[j] = h; rl[j] = l;
    }
    const int pad_end = min(S_, ((n + BM - 1) / BM) * BM);
    for (int j = n + t; j < pad_end; j += 256) {
        rh[j] = __float2bfloat16(0.f);
        rl[j] = __float2bfloat16(0.f);
    }
}

// ---------------------------------------------------------------------------
// Launch
// ---------------------------------------------------------------------------
static void* sym(const void* s) { void* p; cudaGetSymbolAddress(&p, s); return p; }

extern "C" void kernel_launch(void* const* d_in, const int* in_sizes, int n_in,
                              void* d_out, int out_size)
{
    const float* x     = (const float*)d_in[0];
    const float* w_qkv = (const float*)d_in[1];
    const float* w_out = (const float*)d_in[2];
    const float* b_out = (const float*)d_in[3];
    float* out = (float*)d_out;

    float* qkv  = (float*)sym(g_qkv);
    float* simP = (float*)sym(g_sim);
    __nv_bfloat16* xh = (__nv_bfloat16*)sym(g_xh);
    __nv_bfloat16* xl = (__nv_bfloat16*)sym(g_xl);
    __nv_bfloat16* wqt_h = (__nv_bfloat16*)sym(g_wqkvt_h);
    __nv_bfloat16* wqt_l = (__nv_bfloat16*)sym(g_wqkvt_l);
    __nv_bfloat16* wot_h = (__nv_bfloat16*)sym(g_woutt_h);
    __nv_bfloat16* wot_l = (__nv_bfloat16*)sym(g_woutt_l);
    __nv_bfloat16* qkvh = (__nv_bfloat16*)sym(g_qkvh);
    __nv_bfloat16* qkvl = (__nv_bfloat16*)sym(g_qkvl);
    __nv_bfloat16* vth = (__nv_bfloat16*)sym(g_vth);
    __nv_bfloat16* vtl = (__nv_bfloat16*)sym(g_vtl);
    __nv_bfloat16* ath = (__nv_bfloat16*)sym(g_attnh);
    __nv_bfloat16* atl = (__nv_bfloat16*)sym(g_attnl);
    __nv_bfloat16* inh = (__nv_bfloat16*)sym(g_innerh);
    __nv_bfloat16* inl = (__nv_bfloat16*)sym(g_innerl);

    cudaFuncSetAttribute(gemm_mma_kernel,
                         cudaFuncAttributeMaxDynamicSharedMemorySize, SMEM_TOTAL);

    const float scale = 1.0f / 32.0f;   // DIM_INNER^-0.5

    // 1) input splits / weight transposes
    cvt_rm_kernel<<<2048, 256>>>((const float4*)x, (__nv_bfloat162*)xh,
                                 (__nv_bfloat162*)xl, (long long)M1 * DIN / 4);
    cvt_tr_kernel<<<dim3(N1 / 32, DIN / 32, 1), dim3(32, 8)>>>(
        w_qkv, wqt_h, wqt_l, N1, DIN, 0, 0);
    cvt_tr_kernel<<<dim3(DOUT / 32, DINNER / 32, 1), dim3(32, 8)>>>(
        w_out, wot_h, wot_l, DOUT, DINNER, 0, 0);

    // 2) QKV projection -> fp32 qkv + bf16 split (fused)
    {
        GemmArgs a = { xh, xl, wqt_h, wqt_l, qkv, qkvh, qkvl, nullptr,
                       DIN, DIN, DIN, N1, 0, 0, 0, 1.0f, 0, 0 };
        gemm_mma_kernel<<<dim3(N1 / BN, M1 / BM, 1), NTH, SMEM_TOTAL>>>(a);
    }

    // 3) V transpose+split (per batch)
    cvt_tr_kernel<<<dim3(DINNER / 32, S_ / 32, B_), dim3(32, 8)>>>(
        qkv + 2 * DINNER, vth, vtl, N1, S_,
        (long long)S_ * N1, (long long)DINNER * S_);

    // 4) sim = scale * Q K^T (causal blocks only), fp32
    {
        GemmArgs a = { qkvh, qkvl, qkvh + DINNER, qkvl + DINNER, simP,
                       nullptr, nullptr, nullptr,
                       DINNER, N1, N1, S_,
                       (long long)S_ * N1, (long long)S_ * N1, (long long)S_ * S_,
                       scale, 1, 0 };
        gemm_mma_kernel<<<dim3(S_ / BN, S_ / BM, B_), NTH, SMEM_TOTAL>>>(a);
    }

    // 5) softmax -> bf16 split probs (fused)
    softmax_kernel<<<dim3(S_, B_), 256>>>(simP, ath, atl);

    // 6) inner = attn @ V -> bf16 split only (fused, causal K-limit)
    {
        GemmArgs a = { ath, atl, vth, vtl, nullptr, inh, inl, nullptr,
                       S_, S_, S_, DINNER,
                       (long long)S_ * S_, (long long)DINNER * S_,
                       (long long)S_ * DINNER,
                       1.0f, 0, 1 };
        gemm_mma_kernel<<<dim3(DINNER / BN, S_ / BM, B_), NTH, SMEM_TOTAL>>>(a);
    }

    // 7) out = inner @ W_out + b_out (fp32)
    {
        GemmArgs a = { inh, inl, wot_h, wot_l, out, nullptr, nullptr, b_out,
                       DINNER, DINNER, DINNER, DOUT, 0, 0, 0, 1.0f, 0, 0 };
        gemm_mma_kernel<<<dim3(DOUT / BN, M1 / BM, 1), NTH, SMEM_TOTAL>>>(a);
    }
}

// round 5
// speedup vs baseline: 2.3577x; 1.0152x over previous
#include <cuda_runtime.h>
#include <cuda_bf16.h>
#include <cstdint>
#include <float.h>

// ---------------------------------------------------------------------------
// Problem constants
// ---------------------------------------------------------------------------
#define B_     4
#define S_     2048
#define DIN    1024
#define DINNER 1024
#define DOUT   1024
#define M1     (B_ * S_)        // 8192
#define N1     (3 * DINNER)     // 3072

// GEMM tile config (mma.sync)
#define BM 128
#define BN 128
#define BK 32
#define NTH 256                 // 8 warps: 4 (m) x 2 (n)
#define PAD 8
#define LDSROW (BK + PAD)       // 40 bf16 per smem row (80 B)
#define TILE_B (BM * LDSROW * 2)    // 10240 bytes per tile
#define STAGE_B (4 * TILE_B)        // Ah, Al, Bh, Bl = 40960
#define SMEM_TOTAL (2 * STAGE_B)    // 81920

// ---------------------------------------------------------------------------
// PTX helpers (all baseline-PTX legal on compute_103)
// ---------------------------------------------------------------------------
__device__ __forceinline__ uint32_t smem_u32(const void* p) {
    uint32_t a;
    asm("{ .reg .u64 t; cvta.to.shared.u64 t, %1; cvt.u32.u64 %0, t; }"
        : "=r"(a) : "l"(p));
    return a;
}

__device__ __forceinline__ void cp_async16(uint32_t dst, const void* src) {
    asm volatile("cp.async.cg.shared.global [%0], [%1], 16;"
                 :: "r"(dst), "l"(src));
}
#define CP_COMMIT() asm volatile("cp.async.commit_group;" ::: "memory")
#define CP_WAIT(n)  asm volatile("cp.async.wait_group %0;" :: "n"(n) : "memory")

__device__ __forceinline__ void ldmat_x4(uint32_t& r0, uint32_t& r1,
                                         uint32_t& r2, uint32_t& r3,
                                         uint32_t addr) {
    asm volatile("ldmatrix.sync.aligned.m8n8.x4.shared.b16 {%0,%1,%2,%3}, [%4];"
                 : "=r"(r0), "=r"(r1), "=r"(r2), "=r"(r3) : "r"(addr));
}

__device__ __forceinline__ void mma_bf16(float* c, const uint32_t* a,
                                         uint32_t b0, uint32_t b1) {
    asm volatile(
        "mma.sync.aligned.m16n8k16.row.col.f32.bf16.bf16.f32 "
        "{%0,%1,%2,%3}, {%4,%5,%6,%7}, {%8,%9}, {%0,%1,%2,%3};"
        : "+f"(c[0]), "+f"(c[1]), "+f"(c[2]), "+f"(c[3])
        : "r"(a[0]), "r"(a[1]), "r"(a[2]), "r"(a[3]), "r"(b0), "r"(b1));
}

// ---------------------------------------------------------------------------
// Scratch (static device globals)
// ---------------------------------------------------------------------------
__device__ float g_qkv[(size_t)M1 * N1];                     // 96 MB fp32
__device__ float g_sim[(size_t)B_ * S_ * S_];                // 64 MB fp32

__device__ __nv_bfloat16 g_xh[(size_t)M1 * DIN];
__device__ __nv_bfloat16 g_xl[(size_t)M1 * DIN];
__device__ __nv_bfloat16 g_wqkvt_h[(size_t)N1 * DIN];
__device__ __nv_bfloat16 g_wqkvt_l[(size_t)N1 * DIN];
__device__ __nv_bfloat16 g_woutt_h[(size_t)DOUT * DINNER];
__device__ __nv_bfloat16 g_woutt_l[(size_t)DOUT * DINNER];
__device__ __nv_bfloat16 g_qkvh[(size_t)M1 * N1];
__device__ __nv_bfloat16 g_qkvl[(size_t)M1 * N1];
__device__ __nv_bfloat16 g_vth[(size_t)B_ * DINNER * S_];    // V^T per batch
__device__ __nv_bfloat16 g_vtl[(size_t)B_ * DINNER * S_];
__device__ __nv_bfloat16 g_attnh[(size_t)B_ * S_ * S_];
__device__ __nv_bfloat16 g_attnl[(size_t)B_ * S_ * S_];
__device__ __nv_bfloat16 g_innerh[(size_t)M1 * DINNER];
__device__ __nv_bfloat16 g_innerl[(size_t)M1 * DINNER];

// ---------------------------------------------------------------------------
// hi/lo split helpers + conversion kernels
// ---------------------------------------------------------------------------
__device__ __forceinline__ void split2(float x, __nv_bfloat16& h, __nv_bfloat16& l) {
    h = __float2bfloat16(x);
    l = __float2bfloat16(x - __bfloat162float(h));
}

__global__ void cvt_rm_kernel(const float4* __restrict__ src,
                              __nv_bfloat162* __restrict__ h,
                              __nv_bfloat162* __restrict__ l, long long n4) {
    long long i = (long long)blockIdx.x * blockDim.x + threadIdx.x;
    long long stride = (long long)gridDim.x * blockDim.x;
    for (; i < n4; i += stride) {
        float4 v = src[i];
        __nv_bfloat16 h0, h1, h2, h3, l0, l1, l2, l3;
        split2(v.x, h0, l0); split2(v.y, h1, l1);
        split2(v.z, h2, l2); split2(v.w, h3, l3);
        h[2 * i]     = __halves2bfloat162(h0, h1);
        h[2 * i + 1] = __halves2bfloat162(h2, h3);
        l[2 * i]     = __halves2bfloat162(l0, l1);
        l[2 * i + 1] = __halves2bfloat162(l2, l3);
    }
}

// fp32 [R,C] (row stride sld) -> transposed bf16 hi/lo [C,R] (row stride dld)
__global__ void cvt_tr_kernel(const float* __restrict__ src,
                              __nv_bfloat16* __restrict__ h,
                              __nv_bfloat16* __restrict__ l,
                              int sld, int dld,
                              long long sbatch, long long dbatch) {
    __shared__ float t[32][33];
    const int c0 = blockIdx.x * 32;
    const int r0 = blockIdx.y * 32;
    const long long sb = (long long)blockIdx.z * sbatch;
    const long long db = (long long)blockIdx.z * dbatch;
    const int tx = threadIdx.x, ty = threadIdx.y;

    #pragma unroll
    for (int i = 0; i < 32; i += 8)
        t[ty + i][tx] = src[sb + (long long)(r0 + ty + i) * sld + c0 + tx];
    __syncthreads();
    #pragma unroll
    for (int i = 0; i < 32; i += 8) {
        float v = t[tx][ty + i];
        __nv_bfloat16 hh, ll;
        split2(v, hh, ll);
        long long o = db + (long long)(c0 + ty + i) * dld + r0 + tx;
        h[o] = hh;
        l[o] = ll;
    }
}

// ---------------------------------------------------------------------------
// mma.sync bf16 split GEMM: C[M,N] = scale * sum_k A[m,k]*B[n,k] (+bias)
// A: [M,K] K-contiguous ; B: [N,K] K-contiguous
// ---------------------------------------------------------------------------
struct GemmArgs {
    const __nv_bfloat16 *Ah, *Al, *Bh, *Bl;
    float* C;                    // nullable
    __nv_bfloat16 *Ch, *Cl;      // nullable: bf16 hi/lo outputs
    const float* bias;           // nullable
    int K, lda, ldb, ldc;
    long long strideA, strideB, strideC;
    float scale;
    int causal_skip;             // skip CTA if bx > by
    int kmax_mode;               // K_eff = min(K, (by+1)*BM)
};

__device__ __forceinline__ void load_tile(const __nv_bfloat16* __restrict__ g,
                                          int row0, int ld, int k0, uint32_t sm) {
    const int tid = threadIdx.x;
    #pragma unroll
    for (int t = 0; t < 2; t++) {
        int idx = t * NTH + tid;        // 0..511
        int r  = idx >> 2;              // 0..127
        int kc = (idx & 3) * 8;         // 0,8,16,24
        cp_async16(sm + (uint32_t)(r * LDSROW + kc) * 2,
                   g + (long long)(row0 + r) * ld + k0 + kc);
    }
}

__global__ void __launch_bounds__(NTH, 2)
gemm_mma_kernel(GemmArgs args)
{
    const int bx = blockIdx.x, by = blockIdx.y, bb = blockIdx.z;
    if (args.causal_skip && bx > by) return;

    extern __shared__ char smem[];
    const uint32_t smem_base = smem_u32(smem);

    const int tid = threadIdx.x;
    const int wid = tid >> 5;
    const int lane = tid & 31;
    const int wm = wid >> 1;            // 0..3  (32-row slab)
    const int wn = wid & 1;             // 0..1  (64-col slab)
    const int lrow = lane & 15;         // ldmatrix row select
    const int lcol = (lane >> 4) * 8;   // ldmatrix k-half select

    const __nv_bfloat16* Ah = args.Ah + (long long)bb * args.strideA;
    const __nv_bfloat16* Al = args.Al + (long long)bb * args.strideA;
    const __nv_bfloat16* Bh = args.Bh + (long long)bb * args.strideB;
    const __nv_bfloat16* Bl = args.Bl + (long long)bb * args.strideB;

    const int Keff = args.kmax_mode ? min(args.K, (by + 1) * BM) : args.K;
    const int nch = Keff / BK;
    const int arow = by * BM;
    const int brow = bx * BN;

    float acc[2][8][4];
    #pragma unroll
    for (int i = 0; i < 2; i++)
        #pragma unroll
        for (int j = 0; j < 8; j++)
            #pragma unroll
            for (int k = 0; k < 4; k++) acc[i][j][k] = 0.f;

    // prologue: chunk 0 -> stage 0
    load_tile(Ah, arow, args.lda, 0, smem_base);
    load_tile(Al, arow, args.lda, 0, smem_base + TILE_B);
    load_tile(Bh, brow, args.ldb, 0, smem_base + 2 * TILE_B);
    load_tile(Bl, brow, args.ldb, 0, smem_base + 3 * TILE_B);
    CP_COMMIT();

    for (int c = 0; c < nch; c++) {
        const int p = c & 1;
        if (c + 1 < nch) {
            const uint32_t sq = smem_base + (p ^ 1) * STAGE_B;
            const int k0 = (c + 1) * BK;
            load_tile(Ah, arow, args.lda, k0, sq);
            load_tile(Al, arow, args.lda, k0, sq + TILE_B);
            load_tile(Bh, brow, args.ldb, k0, sq + 2 * TILE_B);
            load_tile(Bl, brow, args.ldb, k0, sq + 3 * TILE_B);
            CP_COMMIT();
            CP_WAIT(1);
        } else {
            CP_WAIT(0);
        }
        __syncthreads();

        const uint32_t sp = smem_base + p * STAGE_B;
        #pragma unroll
        for (int kk = 0; kk < 2; kk++) {
            const uint32_t koff = (uint32_t)(kk * 16 + lcol) * 2;
            // A fragments (hi, lo), 2 m16 blocks — live across both j-groups
            uint32_t ah[2][4], al[2][4];
            #pragma unroll
            for (int mi = 0; mi < 2; mi++) {
                uint32_t ra = (uint32_t)((wm * 32 + mi * 16 + lrow) * LDSROW) * 2 + koff;
                ldmat_x4(ah[mi][0], ah[mi][1], ah[mi][2], ah[mi][3], sp + ra);
                ldmat_x4(al[mi][0], al[mi][1], al[mi][2], al[mi][3], sp + TILE_B + ra);
            }
            // B fragments processed in 2 groups of 4 j-blocks (halves live regs)
            #pragma unroll
            for (int jg = 0; jg < 2; jg++) {
                uint32_t bh0[4], bh1[4], bl0[4], bl1[4];
                #pragma unroll
                for (int np = 0; np < 2; np++) {
                    uint32_t rb = (uint32_t)((wn * 64 + (jg * 2 + np) * 16 + lrow)
                                             * LDSROW) * 2 + koff;
                    uint32_t r0, r1, r2, r3;
                    ldmat_x4(r0, r1, r2, r3, sp + 2 * TILE_B + rb);
                    bh0[np * 2] = r0; bh1[np * 2] = r2;
                    bh0[np * 2 + 1] = r1; bh1[np * 2 + 1] = r3;
                    ldmat_x4(r0, r1, r2, r3, sp + 3 * TILE_B + rb);
                    bl0[np * 2] = r0; bl1[np * 2] = r2;
                    bl0[np * 2 + 1] = r1; bl1[np * 2 + 1] = r3;
                }
                // PASS-MAJOR order: consecutive MMAs hit distinct accumulators
                // (same-acc reuse distance = 8 HMMAs instead of 1)
                #pragma unroll
                for (int mi = 0; mi < 2; mi++)
                    #pragma unroll
                    for (int j = 0; j < 4; j++)
                        mma_bf16(acc[mi][jg * 4 + j], ah[mi], bh0[j], bh1[j]);
                #pragma unroll
                for (int mi = 0; mi < 2; mi++)
                    #pragma unroll
                    for (int j = 0; j < 4; j++)
                        mma_bf16(acc[mi][jg * 4 + j], ah[mi], bl0[j], bl1[j]);
                #pragma unroll
                for (int mi = 0; mi < 2; mi++)
                    #pragma unroll
                    for (int j = 0; j < 4; j++)
                        mma_bf16(acc[mi][jg * 4 + j], al[mi], bh0[j], bh1[j]);
            }
        }
        __syncthreads();
    }

    // epilogue
    float* C = args.C ? args.C + (long long)bb * args.strideC : nullptr;
    __nv_bfloat16* Ch = args.Ch ? args.Ch + (long long)bb * args.strideC : nullptr;
    __nv_bfloat16* Cl = args.Cl ? args.Cl + (long long)bb * args.strideC : nullptr;
    const int g = lane >> 2;
    const int tig = lane & 3;

    #pragma unroll
    for (int mi = 0; mi < 2; mi++) {
        #pragma unroll
        for (int j = 0; j < 8; j++) {
            const int row0 = arow + wm * 32 + mi * 16 + g;
            const int col0 = brow + wn * 64 + j * 8 + 2 * tig;
            float v[4];
            #pragma unroll
            for (int k = 0; k < 4; k++) v[k] = acc[mi][j][k] * args.scale;
            if (args.bias) {
                v[0] += args.bias[col0];     v[1] += args.bias[col0 + 1];
                v[2] += args.bias[col0];     v[3] += args.bias[col0 + 1];
            }
            const long long o0 = (long long)row0 * args.ldc + col0;
            const long long o1 = (long long)(row0 + 8) * args.ldc + col0;
            if (C) {
                C[o0] = v[0]; C[o0 + 1] = v[1];
                C[o1] = v[2]; C[o1 + 1] = v[3];
            }
            if (Ch) {
                __nv_bfloat16 h0, h1, h2, h3, l0, l1, l2, l3;
                split2(v[0], h0, l0); split2(v[1], h1, l1);
                split2(v[2], h2, l2); split2(v[3], h3, l3);
                *(__nv_bfloat162*)(Ch + o0) = __halves2bfloat162(h0, h1);
                *(__nv_bfloat162*)(Ch + o1) = __halves2bfloat162(h2, h3);
                *(__nv_bfloat162*)(Cl + o0) = __halves2bfloat162(l0, l1);
                *(__nv_bfloat162*)(Cl + o1) = __halves2bfloat162(l2, l3);
            }
        }
    }
}

// ---------------------------------------------------------------------------
// Causal row softmax: fp32 sim -> bf16 hi/lo probs, zero-filled to 128 edge
// ---------------------------------------------------------------------------
__global__ void __launch_bounds__(256)
softmax_kernel(const float* __restrict__ sim,
               __nv_bfloat16* __restrict__ ph, __nv_bfloat16* __restrict__ pl)
{
    const int i = blockIdx.x;
    const int b = blockIdx.y;
    const float* row = sim + ((size_t)b * S_ + i) * S_;
    __nv_bfloat16* rh = ph + ((size_t)b * S_ + i) * S_;
    __nv_bfloat16* rl = pl + ((size_t)b * S_ + i) * S_;
    const int n = i + 1;

    __shared__ float red[256];
    const int t = threadIdx.x;

    float m = -FLT_MAX;
    for (int j = t; j < n; j += 256) m = fmaxf(m, row[j]);
    red[t] = m; __syncthreads();
    for (int s = 128; s > 0; s >>= 1) {
        if (t < s) red[t] = fmaxf(red[t], red[t + s]);
        __syncthreads();
    }
    m = red[0]; __syncthreads();

    float sum = 0.f;
    for (int j = t; j < n; j += 256) sum += expf(row[j] - m);
    red[t] = sum; __syncthreads();
    for (int s = 128; s > 0; s >>= 1) {
        if (t < s) red[t] += red[t + s];
        __syncthreads();
    }
    const float inv = 1.f / red[0];
    __syncthreads();

    for (int j = t; j < n; j += 256) {
        float p = expf(row[j] - m) * inv;
        __nv_bfloat16 h, l;
        split2(p, h, l);
        rh[j] = h; rl[j] = l;
    }
    const int pad_end = min(S_, ((n + BM - 1) / BM) * BM);
    for (int j = n + t; j < pad_end; j += 256) {
        rh[j] = __float2bfloat16(0.f);
        rl[j] = __float2bfloat16(0.f);
    }
}

// ---------------------------------------------------------------------------
// Launch
// ---------------------------------------------------------------------------
static void* sym(const void* s) { void* p; cudaGetSymbolAddress(&p, s); return p; }

extern "C" void kernel_launch(void* const* d_in, const int* in_sizes, int n_in,
                              void* d_out, int out_size)
{
    const float* x     = (const float*)d_in[0];
    const float* w_qkv = (const float*)d_in[1];
    const float* w_out = (const float*)d_in[2];
    const float* b_out = (const float*)d_in[3];
    float* out = (float*)d_out;

    float* qkv  = (float*)sym(g_qkv);
    float* simP = (float*)sym(g_sim);
    __nv_bfloat16* xh = (__nv_bfloat16*)sym(g_xh);
    __nv_bfloat16* xl = (__nv_bfloat16*)sym(g_xl);
    __nv_bfloat16* wqt_h = (__nv_bfloat16*)sym(g_wqkvt_h);
    __nv_bfloat16* wqt_l = (__nv_bfloat16*)sym(g_wqkvt_l);
    __nv_bfloat16* wot_h = (__nv_bfloat16*)sym(g_woutt_h);
    __nv_bfloat16* wot_l = (__nv_bfloat16*)sym(g_woutt_l);
    __nv_bfloat16* qkvh = (__nv_bfloat16*)sym(g_qkvh);
    __nv_bfloat16* qkvl = (__nv_bfloat16*)sym(g_qkvl);
    __nv_bfloat16* vth = (__nv_bfloat16*)sym(g_vth);
    __nv_bfloat16* vtl = (__nv_bfloat16*)sym(g_vtl);
    __nv_bfloat16* ath = (__nv_bfloat16*)sym(g_attnh);
    __nv_bfloat16* atl = (__nv_bfloat16*)sym(g_attnl);
    __nv_bfloat16* inh = (__nv_bfloat16*)sym(g_innerh);
    __nv_bfloat16* inl = (__nv_bfloat16*)sym(g_innerl);

    cudaFuncSetAttribute(gemm_mma_kernel,
                         cudaFuncAttributeMaxDynamicSharedMemorySize, SMEM_TOTAL);

    const float scale = 1.0f / 32.0f;   // DIM_INNER^-0.5

    // 1) input splits / weight transposes
    cvt_rm_kernel<<<2048, 256>>>((const float4*)x, (__nv_bfloat162*)xh,
                                 (__nv_bfloat162*)xl, (long long)M1 * DIN / 4);
    cvt_tr_kernel<<<dim3(N1 / 32, DIN / 32, 1), dim3(32, 8)>>>(
        w_qkv, wqt_h, wqt_l, N1, DIN, 0, 0);
    cvt_tr_kernel<<<dim3(DOUT / 32, DINNER / 32, 1), dim3(32, 8)>>>(
        w_out, wot_h, wot_l, DOUT, DINNER, 0, 0);

    // 2) QKV projection -> fp32 qkv + bf16 split (fused)
    {
        GemmArgs a = { xh, xl, wqt_h, wqt_l, qkv, qkvh, qkvl, nullptr,
                       DIN, DIN, DIN, N1, 0, 0, 0, 1.0f, 0, 0 };
        gemm_mma_kernel<<<dim3(N1 / BN, M1 / BM, 1), NTH, SMEM_TOTAL>>>(a);
    }

    // 3) V transpose+split (per batch)
    cvt_tr_kernel<<<dim3(DINNER / 32, S_ / 32, B_), dim3(32, 8)>>>(
        qkv + 2 * DINNER, vth, vtl, N1, S_,
        (long long)S_ * N1, (long long)DINNER * S_);

    // 4) sim = scale * Q K^T (causal blocks only), fp32
    {
        GemmArgs a = { qkvh, qkvl, qkvh + DINNER, qkvl + DINNER, simP,
                       nullptr, nullptr, nullptr,
                       DINNER, N1, N1, S_,
                       (long long)S_ * N1, (long long)S_ * N1, (long long)S_ * S_,
                       scale, 1, 0 };
        gemm_mma_kernel<<<dim3(S_ / BN, S_ / BM, B_), NTH, SMEM_TOTAL>>>(a);
    }

    // 5) softmax -> bf16 split probs (fused)
    softmax_kernel<<<dim3(S_, B_), 256>>>(simP, ath, atl);

    // 6) inner = attn @ V -> bf16 split only (fused, causal K-limit)
    {
        GemmArgs a = { ath, atl, vth, vtl, nullptr, inh, inl, nullptr,
                       S_, S_, S_, DINNER,
                       (long long)S_ * S_, (long long)DINNER * S_,
                       (long long)S_ * DINNER,
                       1.0f, 0, 1 };
        gemm_mma_kernel<<<dim3(DINNER / BN, S_ / BM, B_), NTH, SMEM_TOTAL>>>(a);
    }

    // 7) out = inner @ W_out + b_out (fp32)
    {
        GemmArgs a = { inh, inl, wot_h, wot_l, out, nullptr, nullptr, b_out,
                       DINNER, DINNER, DINNER, DOUT, 0, 0, 0, 1.0f, 0, 0 };
        gemm_mma_kernel<<<dim3(DOUT / BN, M1 / BM, 1), NTH, SMEM_TOTAL>>>(a);
    }
}

// round 6
// speedup vs baseline: 2.3615x; 1.0016x over previous
#include <cuda_runtime.h>
#include <cuda_bf16.h>
#include <cstdint>
#include <float.h>

// ---------------------------------------------------------------------------
// Problem constants
// ---------------------------------------------------------------------------
#define B_     4
#define S_     2048
#define DIN    1024
#define DINNER 1024
#define DOUT   1024
#define M1     (B_ * S_)        // 8192
#define N1     (3 * DINNER)     // 3072

// GEMM tile config (mma.sync)
#define BM 128
#define BN 128
#define BK 32
#define NTH 256                 // 8 warps: 4 (m) x 2 (n)
#define PAD 8
#define LDSROW (BK + PAD)       // 40 bf16 per smem row (80 B)
#define TILE_B (BM * LDSROW * 2)    // 10240 bytes per tile
#define STAGE_B (4 * TILE_B)        // Ah, Al, Bh, Bl = 40960
#define SMEM_TOTAL (2 * STAGE_B)    // 81920

// ---------------------------------------------------------------------------
// PTX helpers (all baseline-PTX legal on compute_103)
// ---------------------------------------------------------------------------
__device__ __forceinline__ uint32_t smem_u32(const void* p) {
    uint32_t a;
    asm("{ .reg .u64 t; cvta.to.shared.u64 t, %1; cvt.u32.u64 %0, t; }"
        : "=r"(a) : "l"(p));
    return a;
}

__device__ __forceinline__ void cp_async16(uint32_t dst, const void* src) {
    asm volatile("cp.async.cg.shared.global [%0], [%1], 16;"
                 :: "r"(dst), "l"(src));
}
#define CP_COMMIT() asm volatile("cp.async.commit_group;" ::: "memory")
#define CP_WAIT(n)  asm volatile("cp.async.wait_group %0;" :: "n"(n) : "memory")

__device__ __forceinline__ void ldmat_x4(uint32_t& r0, uint32_t& r1,
                                         uint32_t& r2, uint32_t& r3,
                                         uint32_t addr) {
    asm volatile("ldmatrix.sync.aligned.m8n8.x4.shared.b16 {%0,%1,%2,%3}, [%4];"
                 : "=r"(r0), "=r"(r1), "=r"(r2), "=r"(r3) : "r"(addr));
}

__device__ __forceinline__ void mma_bf16(float* c, const uint32_t* a,
                                         uint32_t b0, uint32_t b1) {
    asm volatile(
        "mma.sync.aligned.m16n8k16.row.col.f32.bf16.bf16.f32 "
        "{%0,%1,%2,%3}, {%4,%5,%6,%7}, {%8,%9}, {%0,%1,%2,%3};"
        : "+f"(c[0]), "+f"(c[1]), "+f"(c[2]), "+f"(c[3])
        : "r"(a[0]), "r"(a[1]), "r"(a[2]), "r"(a[3]), "r"(b0), "r"(b1));
}

// ---------------------------------------------------------------------------
// Scratch (static device globals)
// ---------------------------------------------------------------------------
__device__ float g_qkv[(size_t)M1 * N1];                     // 96 MB fp32
__device__ float g_sim[(size_t)B_ * S_ * S_];                // 64 MB fp32

__device__ __nv_bfloat16 g_xh[(size_t)M1 * DIN];
__device__ __nv_bfloat16 g_xl[(size_t)M1 * DIN];
__device__ __nv_bfloat16 g_wqkvt_h[(size_t)N1 * DIN];
__device__ __nv_bfloat16 g_wqkvt_l[(size_t)N1 * DIN];
__device__ __nv_bfloat16 g_woutt_h[(size_t)DOUT * DINNER];
__device__ __nv_bfloat16 g_woutt_l[(size_t)DOUT * DINNER];
__device__ __nv_bfloat16 g_qkvh[(size_t)M1 * N1];
__device__ __nv_bfloat16 g_qkvl[(size_t)M1 * N1];
__device__ __nv_bfloat16 g_vth[(size_t)B_ * DINNER * S_];    // V^T per batch
__device__ __nv_bfloat16 g_vtl[(size_t)B_ * DINNER * S_];
__device__ __nv_bfloat16 g_attnh[(size_t)B_ * S_ * S_];
__device__ __nv_bfloat16 g_attnl[(size_t)B_ * S_ * S_];
__device__ __nv_bfloat16 g_innerh[(size_t)M1 * DINNER];
__device__ __nv_bfloat16 g_innerl[(size_t)M1 * DINNER];

// ---------------------------------------------------------------------------
// hi/lo split helpers + conversion kernels
// ---------------------------------------------------------------------------
__device__ __forceinline__ void split2(float x, __nv_bfloat16& h, __nv_bfloat16& l) {
    h = __float2bfloat16(x);
    l = __float2bfloat16(x - __bfloat162float(h));
}

__global__ void cvt_rm_kernel(const float4* __restrict__ src,
                              __nv_bfloat162* __restrict__ h,
                              __nv_bfloat162* __restrict__ l, long long n4) {
    long long i = (long long)blockIdx.x * blockDim.x + threadIdx.x;
    long long stride = (long long)gridDim.x * blockDim.x;
    for (; i < n4; i += stride) {
        float4 v = src[i];
        __nv_bfloat16 h0, h1, h2, h3, l0, l1, l2, l3;
        split2(v.x, h0, l0); split2(v.y, h1, l1);
        split2(v.z, h2, l2); split2(v.w, h3, l3);
        h[2 * i]     = __halves2bfloat162(h0, h1);
        h[2 * i + 1] = __halves2bfloat162(h2, h3);
        l[2 * i]     = __halves2bfloat162(l0, l1);
        l[2 * i + 1] = __halves2bfloat162(l2, l3);
    }
}

// fp32 [R,C] (row stride sld) -> transposed bf16 hi/lo [C,R] (row stride dld)
__global__ void cvt_tr_kernel(const float* __restrict__ src,
                              __nv_bfloat16* __restrict__ h,
                              __nv_bfloat16* __restrict__ l,
                              int sld, int dld,
                              long long sbatch, long long dbatch) {
    __shared__ float t[32][33];
    const int c0 = blockIdx.x * 32;
    const int r0 = blockIdx.y * 32;
    const long long sb = (long long)blockIdx.z * sbatch;
    const long long db = (long long)blockIdx.z * dbatch;
    const int tx = threadIdx.x, ty = threadIdx.y;

    #pragma unroll
    for (int i = 0; i < 32; i += 8)
        t[ty + i][tx] = src[sb + (long long)(r0 + ty + i) * sld + c0 + tx];
    __syncthreads();
    #pragma unroll
    for (int i = 0; i < 32; i += 8) {
        float v = t[tx][ty + i];
        __nv_bfloat16 hh, ll;
        split2(v, hh, ll);
        long long o = db + (long long)(c0 + ty + i) * dld + r0 + tx;
        h[o] = hh;
        l[o] = ll;
    }
}

// ---------------------------------------------------------------------------
// mma.sync bf16 split GEMM: C[M,N] = scale * sum_k A[m,k]*B[n,k] (+bias)
// A: [M,K] K-contiguous ; B: [N,K] K-contiguous
// ---------------------------------------------------------------------------
struct GemmArgs {
    const __nv_bfloat16 *Ah, *Al, *Bh, *Bl;
    float* C;                    // nullable
    __nv_bfloat16 *Ch, *Cl;      // nullable: bf16 hi/lo outputs
    const float* bias;           // nullable
    int K, lda, ldb, ldc;
    long long strideA, strideB, strideC;
    float scale;
    int causal_skip;             // skip CTA if bx > by
    int kmax_mode;               // K_eff = min(K, (by+1)*BM)
};

__device__ __forceinline__ void load_tile(const __nv_bfloat16* __restrict__ g,
                                          int row0, int ld, int k0, uint32_t sm) {
    const int tid = threadIdx.x;
    #pragma unroll
    for (int t = 0; t < 2; t++) {
        int idx = t * NTH + tid;        // 0..511
        int r  = idx >> 2;              // 0..127
        int kc = (idx & 3) * 8;         // 0,8,16,24
        cp_async16(sm + (uint32_t)(r * LDSROW + kc) * 2,
                   g + (long long)(row0 + r) * ld + k0 + kc);
    }
}

__global__ void __launch_bounds__(NTH, 2)
gemm_mma_kernel(GemmArgs args)
{
    const int bx = blockIdx.x, by = blockIdx.y, bb = blockIdx.z;
    if (args.causal_skip && bx > by) return;

    extern __shared__ char smem[];
    const uint32_t smem_base = smem_u32(smem);

    const int tid = threadIdx.x;
    const int wid = tid >> 5;
    const int lane = tid & 31;
    const int wm = wid >> 1;            // 0..3  (32-row slab)
    const int wn = wid & 1;             // 0..1  (64-col slab)
    const int lrow = lane & 15;         // ldmatrix row select
    const int lcol = (lane >> 4) * 8;   // ldmatrix k-half select

    const __nv_bfloat16* Ah = args.Ah + (long long)bb * args.strideA;
    const __nv_bfloat16* Al = args.Al + (long long)bb * args.strideA;
    const __nv_bfloat16* Bh = args.Bh + (long long)bb * args.strideB;
    const __nv_bfloat16* Bl = args.Bl + (long long)bb * args.strideB;

    const int Keff = args.kmax_mode ? min(args.K, (by + 1) * BM) : args.K;
    const int nch = Keff / BK;
    const int arow = by * BM;
    const int brow = bx * BN;

    float acc[2][8][4];
    #pragma unroll
    for (int i = 0; i < 2; i++)
        #pragma unroll
        for (int j = 0; j < 8; j++)
            #pragma unroll
            for (int k = 0; k < 4; k++) acc[i][j][k] = 0.f;

    // prologue: chunk 0 -> stage 0
    load_tile(Ah, arow, args.lda, 0, smem_base);
    load_tile(Al, arow, args.lda, 0, smem_base + TILE_B);
    load_tile(Bh, brow, args.ldb, 0, smem_base + 2 * TILE_B);
    load_tile(Bl, brow, args.ldb, 0, smem_base + 3 * TILE_B);
    CP_COMMIT();

    for (int c = 0; c < nch; c++) {
        const int p = c & 1;
        if (c + 1 < nch) {
            const uint32_t sq = smem_base + (p ^ 1) * STAGE_B;
            const int k0 = (c + 1) * BK;
            load_tile(Ah, arow, args.lda, k0, sq);
            load_tile(Al, arow, args.lda, k0, sq + TILE_B);
            load_tile(Bh, brow, args.ldb, k0, sq + 2 * TILE_B);
            load_tile(Bl, brow, args.ldb, k0, sq + 3 * TILE_B);
            CP_COMMIT();
            CP_WAIT(1);
        } else {
            CP_WAIT(0);
        }
        __syncthreads();

        const uint32_t sp = smem_base + p * STAGE_B;
        #pragma unroll
        for (int kk = 0; kk < 2; kk++) {
            const uint32_t koff = (uint32_t)(kk * 16 + lcol) * 2;
            // A fragments (hi, lo), 2 m16 blocks — live across both j-groups
            uint32_t ah[2][4], al[2][4];
            #pragma unroll
            for (int mi = 0; mi < 2; mi++) {
                uint32_t ra = (uint32_t)((wm * 32 + mi * 16 + lrow) * LDSROW) * 2 + koff;
                ldmat_x4(ah[mi][0], ah[mi][1], ah[mi][2], ah[mi][3], sp + ra);
                ldmat_x4(al[mi][0], al[mi][1], al[mi][2], al[mi][3], sp + TILE_B + ra);
            }
            // B fragments processed in 2 groups of 4 j-blocks (halves live regs)
            #pragma unroll
            for (int jg = 0; jg < 2; jg++) {
                uint32_t bh0[4], bh1[4], bl0[4], bl1[4];
                #pragma unroll
                for (int np = 0; np < 2; np++) {
                    uint32_t rb = (uint32_t)((wn * 64 + (jg * 2 + np) * 16 + lrow)
                                             * LDSROW) * 2 + koff;
                    uint32_t r0, r1, r2, r3;
                    ldmat_x4(r0, r1, r2, r3, sp + 2 * TILE_B + rb);
                    bh0[np * 2] = r0; bh1[np * 2] = r2;
                    bh0[np * 2 + 1] = r1; bh1[np * 2 + 1] = r3;
                    ldmat_x4(r0, r1, r2, r3, sp + 3 * TILE_B + rb);
                    bl0[np * 2] = r0; bl1[np * 2] = r2;
                    bl0[np * 2 + 1] = r1; bl1[np * 2 + 1] = r3;
                }
                // PASS-MAJOR order: consecutive MMAs hit distinct accumulators
                // (same-acc reuse distance = 8 HMMAs instead of 1)
                #pragma unroll
                for (int mi = 0; mi < 2; mi++)
                    #pragma unroll
                    for (int j = 0; j < 4; j++)
                        mma_bf16(acc[mi][jg * 4 + j], ah[mi], bh0[j], bh1[j]);
                #pragma unroll
                for (int mi = 0; mi < 2; mi++)
                    #pragma unroll
                    for (int j = 0; j < 4; j++)
                        mma_bf16(acc[mi][jg * 4 + j], ah[mi], bl0[j], bl1[j]);
                #pragma unroll
                for (int mi = 0; mi < 2; mi++)
                    #pragma unroll
                    for (int j = 0; j < 4; j++)
                        mma_bf16(acc[mi][jg * 4 + j], al[mi], bh0[j], bh1[j]);
            }
        }
        __syncthreads();
    }

    // epilogue
    float* C = args.C ? args.C + (long long)bb * args.strideC : nullptr;
    __nv_bfloat16* Ch = args.Ch ? args.Ch + (long long)bb * args.strideC : nullptr;
    __nv_bfloat16* Cl = args.Cl ? args.Cl + (long long)bb * args.strideC : nullptr;
    const int g = lane >> 2;
    const int tig = lane & 3;

    #pragma unroll
    for (int mi = 0; mi < 2; mi++) {
        #pragma unroll
        for (int j = 0; j < 8; j++) {
            const int row0 = arow + wm * 32 + mi * 16 + g;
            const int col0 = brow + wn * 64 + j * 8 + 2 * tig;
            float v[4];
            #pragma unroll
            for (int k = 0; k < 4; k++) v[k] = acc[mi][j][k] * args.scale;
            if (args.bias) {
                v[0] += args.bias[col0];     v[1] += args.bias[col0 + 1];
                v[2] += args.bias[col0];     v[3] += args.bias[col0 + 1];
            }
            const long long o0 = (long long)row0 * args.ldc + col0;
            const long long o1 = (long long)(row0 + 8) * args.ldc + col0;
            if (C) {
                C[o0] = v[0]; C[o0 + 1] = v[1];
                C[o1] = v[2]; C[o1 + 1] = v[3];
            }
            if (Ch) {
                __nv_bfloat16 h0, h1, h2, h3, l0, l1, l2, l3;
                split2(v[0], h0, l0); split2(v[1], h1, l1);
                split2(v[2], h2, l2); split2(v[3], h3, l3);
                *(__nv_bfloat162*)(Ch + o0) = __halves2bfloat162(h0, h1);
                *(__nv_bfloat162*)(Ch + o1) = __halves2bfloat162(h2, h3);
                *(__nv_bfloat162*)(Cl + o0) = __halves2bfloat162(l0, l1);
                *(__nv_bfloat162*)(Cl + o1) = __halves2bfloat162(l2, l3);
            }
        }
    }
}

// ---------------------------------------------------------------------------
// Causal row softmax: fp32 sim -> bf16 hi/lo probs, zero-filled to 128 edge
// ---------------------------------------------------------------------------
__global__ void __launch_bounds__(256)
softmax_kernel(const float* __restrict__ sim,
               __nv_bfloat16* __restrict__ ph, __nv_bfloat16* __restrict__ pl)
{
    const int i = blockIdx.x;
    const int b = blockIdx.y;
    const float* row = sim + ((size_t)b * S_ + i) * S_;
    __nv_bfloat16* rh = ph + ((size_t)b * S_ + i) * S_;
    __nv_bfloat16* rl = pl + ((size_t)b * S_ + i) * S_;
    const int n = i + 1;

    __shared__ float red[256];
    const int t = threadIdx.x;

    float m = -FLT_MAX;
    for (int j = t; j < n; j += 256) m = fmaxf(m, row[j]);
    red[t] = m; __syncthreads();
    for (int s = 128; s > 0; s >>= 1) {
        if (t < s) red[t] = fmaxf(red[t], red[t + s]);
        __syncthreads();
    }
    m = red[0]; __syncthreads();

    float sum = 0.f;
    for (int j = t; j < n; j += 256) sum += expf(row[j] - m);
    red[t] = sum; __syncthreads();
    for (int s = 128; s > 0; s >>= 1) {
        if (t < s) red[t] += red[t + s];
        __syncthreads();
    }
    const float inv = 1.f / red[0];
    __syncthreads();

    for (int j = t; j < n; j += 256) {
        float p = expf(row[j] - m) * inv;
        __nv_bfloat16 h, l;
        split2(p, h, l);
        rh[j] = h; rl[j] = l;
    }
    const int pad_end = min(S_, ((n + BM - 1) / BM) * BM);
    for (int j = n + t; j < pad_end; j += 256) {
        rh[j] = __float2bfloat16(0.f);
        rl[j] = __float2bfloat16(0.f);
    }
}

// ---------------------------------------------------------------------------
// Launch
// ---------------------------------------------------------------------------
static void* sym(const void* s) { void* p; cudaGetSymbolAddress(&p, s); return p; }

extern "C" void kernel_launch(void* const* d_in, const int* in_sizes, int n_in,
                              void* d_out, int out_size)
{
    const float* x     = (const float*)d_in[0];
    const float* w_qkv = (const float*)d_in[1];
    const float* w_out = (const float*)d_in[2];
    const float* b_out = (const float*)d_in[3];
    float* out = (float*)d_out;

    float* qkv  = (float*)sym(g_qkv);
    float* simP = (float*)sym(g_sim);
    __nv_bfloat16* xh = (__nv_bfloat16*)sym(g_xh);
    __nv_bfloat16* xl = (__nv_bfloat16*)sym(g_xl);
    __nv_bfloat16* wqt_h = (__nv_bfloat16*)sym(g_wqkvt_h);
    __nv_bfloat16* wqt_l = (__nv_bfloat16*)sym(g_wqkvt_l);
    __nv_bfloat16* wot_h = (__nv_bfloat16*)sym(g_woutt_h);
    __nv_bfloat16* wot_l = (__nv_bfloat16*)sym(g_woutt_l);
    __nv_bfloat16* qkvh = (__nv_bfloat16*)sym(g_qkvh);
    __nv_bfloat16* qkvl = (__nv_bfloat16*)sym(g_qkvl);
    __nv_bfloat16* vth = (__nv_bfloat16*)sym(g_vth);
    __nv_bfloat16* vtl = (__nv_bfloat16*)sym(g_vtl);
    __nv_bfloat16* ath = (__nv_bfloat16*)sym(g_attnh);
    __nv_bfloat16* atl = (__nv_bfloat16*)sym(g_attnl);
    __nv_bfloat16* inh = (__nv_bfloat16*)sym(g_innerh);
    __nv_bfloat16* inl = (__nv_bfloat16*)sym(g_innerl);

    cudaFuncSetAttribute(gemm_mma_kernel,
                         cudaFuncAttributeMaxDynamicSharedMemorySize, SMEM_TOTAL);

    const float scale = 1.0f / 32.0f;   // DIM_INNER^-0.5

    // 1) input splits / weight transposes
    cvt_rm_kernel<<<2048, 256>>>((const float4*)x, (__nv_bfloat162*)xh,
                                 (__nv_bfloat162*)xl, (long long)M1 * DIN / 4);
    cvt_tr_kernel<<<dim3(N1 / 32, DIN / 32, 1), dim3(32, 8)>>>(
        w_qkv, wqt_h, wqt_l, N1, DIN, 0, 0);
    cvt_tr_kernel<<<dim3(DOUT / 32, DINNER / 32, 1), dim3(32, 8)>>>(
        w_out, wot_h, wot_l, DOUT, DINNER, 0, 0);

    // 2) QKV projection -> fp32 qkv + bf16 split (fused)
    {
        GemmArgs a = { xh, xl, wqt_h, wqt_l, qkv, qkvh, qkvl, nullptr,
                       DIN, DIN, DIN, N1, 0, 0, 0, 1.0f, 0, 0 };
        gemm_mma_kernel<<<dim3(N1 / BN, M1 / BM, 1), NTH, SMEM_TOTAL>>>(a);
    }

    // 3) V transpose+split (per batch)
    cvt_tr_kernel<<<dim3(DINNER / 32, S_ / 32, B_), dim3(32, 8)>>>(
        qkv + 2 * DINNER, vth, vtl, N1, S_,
        (long long)S_ * N1, (long long)DINNER * S_);

    // 4) sim = scale * Q K^T (causal blocks only), fp32
    {
        GemmArgs a = { qkvh, qkvl, qkvh + DINNER, qkvl + DINNER, simP,
                       nullptr, nullptr, nullptr,
                       DINNER, N1, N1, S_,
                       (long long)S_ * N1, (long long)S_ * N1, (long long)S_ * S_,
                       scale, 1, 0 };
        gemm_mma_kernel<<<dim3(S_ / BN, S_ / BM, B_), NTH, SMEM_TOTAL>>>(a);
    }

    // 5) softmax -> bf16 split probs (fused)
    softmax_kernel<<<dim3(S_, B_), 256>>>(simP, ath, atl);

    // 6) inner = attn @ V -> bf16 split only (fused, causal K-limit)
    {
        GemmArgs a = { ath, atl, vth, vtl, nullptr, inh, inl, nullptr,
                       S_, S_, S_, DINNER,
                       (long long)S_ * S_, (long long)DINNER * S_,
                       (long long)S_ * DINNER,
                       1.0f, 0, 1 };
        gemm_mma_kernel<<<dim3(DINNER / BN, S_ / BM, B_), NTH, SMEM_TOTAL>>>(a);
    }

    // 7) out = inner @ W_out + b_out (fp32)
    {
        GemmArgs a = { inh, inl, wot_h, wot_l, out, nullptr, nullptr, b_out,
                       DINNER, DINNER, DINNER, DOUT, 0, 0, 0, 1.0f, 0, 0 };
        gemm_mma_kernel<<<dim3(DOUT / BN, M1 / BM, 1), NTH, SMEM_TOTAL>>>(a);
    }
}

// round 7
// speedup vs baseline: 3.3831x; 1.4326x over previous
#include <cuda_runtime.h>
#include <cuda_fp16.h>
#include <cstdint>
#include <float.h>

// ---------------------------------------------------------------------------
// Problem constants
// ---------------------------------------------------------------------------
#define B_     4
#define S_     2048
#define DIN    1024
#define DINNER 1024
#define DOUT   1024
#define M1     (B_ * S_)        // 8192
#define N1     (3 * DINNER)     // 3072

// GEMM tile config (mma.sync)
#define BM 128
#define BN 128
#define BK 32
#define NTH 256                 // 8 warps: 4 (m) x 2 (n)
#define PAD 8
#define LDSROW (BK + PAD)       // 40 fp16 per smem row (80 B)
#define TILE_B (BM * LDSROW * 2)    // 10240 bytes per tile
#define STAGE_B (2 * TILE_B)        // A, B = 20480
#define SMEM_TOTAL (2 * STAGE_B)    // 40960

// ---------------------------------------------------------------------------
// PTX helpers (all baseline-PTX legal on compute_103)
// ---------------------------------------------------------------------------
__device__ __forceinline__ uint32_t smem_u32(const void* p) {
    uint32_t a;
    asm("{ .reg .u64 t; cvta.to.shared.u64 t, %1; cvt.u32.u64 %0, t; }"
        : "=r"(a) : "l"(p));
    return a;
}

__device__ __forceinline__ void cp_async16(uint32_t dst, const void* src) {
    asm volatile("cp.async.cg.shared.global [%0], [%1], 16;"
                 :: "r"(dst), "l"(src));
}
#define CP_COMMIT() asm volatile("cp.async.commit_group;" ::: "memory")
#define CP_WAIT(n)  asm volatile("cp.async.wait_group %0;" :: "n"(n) : "memory")

__device__ __forceinline__ void ldmat_x4(uint32_t& r0, uint32_t& r1,
                                         uint32_t& r2, uint32_t& r3,
                                         uint32_t addr) {
    asm volatile("ldmatrix.sync.aligned.m8n8.x4.shared.b16 {%0,%1,%2,%3}, [%4];"
                 : "=r"(r0), "=r"(r1), "=r"(r2), "=r"(r3) : "r"(addr));
}

__device__ __forceinline__ void mma_fp16(float* c, const uint32_t* a,
                                         uint32_t b0, uint32_t b1) {
    asm volatile(
        "mma.sync.aligned.m16n8k16.row.col.f32.f16.f16.f32 "
        "{%0,%1,%2,%3}, {%4,%5,%6,%7}, {%8,%9}, {%0,%1,%2,%3};"
        : "+f"(c[0]), "+f"(c[1]), "+f"(c[2]), "+f"(c[3])
        : "r"(a[0]), "r"(a[1]), "r"(a[2]), "r"(a[3]), "r"(b0), "r"(b1));
}

// ---------------------------------------------------------------------------
// Scratch (static device globals)
// ---------------------------------------------------------------------------
__device__ float g_qkv[(size_t)M1 * N1];                 // 96 MB fp32
__device__ float g_sim[(size_t)B_ * S_ * S_];            // 64 MB fp32

__device__ __half g_xh[(size_t)M1 * DIN];                // 16 MB
__device__ __half g_wqkvt[(size_t)N1 * DIN];             // 6 MB (transposed)
__device__ __half g_woutt[(size_t)DOUT * DINNER];        // 2 MB (transposed)
__device__ __half g_qkvh[(size_t)M1 * N1];               // 48 MB
__device__ __half g_vt[(size_t)B_ * DINNER * S_];        // 16 MB (V^T per batch)
__device__ __half g_attn[(size_t)B_ * S_ * S_];          // 32 MB
__device__ __half g_inner[(size_t)M1 * DINNER];          // 16 MB

// ---------------------------------------------------------------------------
// Conversion kernels
// ---------------------------------------------------------------------------
__global__ void cvt_rm_kernel(const float4* __restrict__ src,
                              __half2* __restrict__ h, long long n4) {
    long long i = (long long)blockIdx.x * blockDim.x + threadIdx.x;
    long long stride = (long long)gridDim.x * blockDim.x;
    for (; i < n4; i += stride) {
        float4 v = src[i];
        h[2 * i]     = __floats2half2_rn(v.x, v.y);
        h[2 * i + 1] = __floats2half2_rn(v.z, v.w);
    }
}

// fp32 [R,C] (row stride sld) -> transposed fp16 [C,R] (row stride dld)
__global__ void cvt_tr_kernel(const float* __restrict__ src,
                              __half* __restrict__ h,
                              int sld, int dld,
                              long long sbatch, long long dbatch) {
    __shared__ float t[32][33];
    const int c0 = blockIdx.x * 32;
    const int r0 = blockIdx.y * 32;
    const long long sb = (long long)blockIdx.z * sbatch;
    const long long db = (long long)blockIdx.z * dbatch;
    const int tx = threadIdx.x, ty = threadIdx.y;

    #pragma unroll
    for (int i = 0; i < 32; i += 8)
        t[ty + i][tx] = src[sb + (long long)(r0 + ty + i) * sld + c0 + tx];
    __syncthreads();
    #pragma unroll
    for (int i = 0; i < 32; i += 8) {
        long long o = db + (long long)(c0 + ty + i) * dld + r0 + tx;
        h[o] = __float2half(t[tx][ty + i]);
    }
}

// ---------------------------------------------------------------------------
// mma.sync fp16 GEMM: C[M,N] = scale * sum_k A[m,k]*B[n,k] (+bias)
// A: [M,K] K-contiguous ; B: [N,K] K-contiguous
// ---------------------------------------------------------------------------
struct GemmArgs {
    const __half *A, *B;
    float* C;                    // nullable fp32 out
    __half* Ch;                  // nullable fp16 out
    const float* bias;           // nullable
    int K, lda, ldb, ldc;
    long long strideA, strideB, strideC;
    float scale;
    int causal_skip;             // skip CTA if bx > by
    int kmax_mode;               // K_eff = min(K, (by+1)*BM)
};

__device__ __forceinline__ void load_tile(const __half* __restrict__ g,
                                          int row0, int ld, int k0, uint32_t sm) {
    const int tid = threadIdx.x;
    #pragma unroll
    for (int t = 0; t < 2; t++) {
        int idx = t * NTH + tid;        // 0..511
        int r  = idx >> 2;              // 0..127
        int kc = (idx & 3) * 8;         // 0,8,16,24
        cp_async16(sm + (uint32_t)(r * LDSROW + kc) * 2,
                   g + (long long)(row0 + r) * ld + k0 + kc);
    }
}

__global__ void __launch_bounds__(NTH, 2)
gemm_mma_kernel(GemmArgs args)
{
    const int bx = blockIdx.x, by = blockIdx.y, bb = blockIdx.z;
    if (args.causal_skip && bx > by) return;

    extern __shared__ char smem[];
    const uint32_t smem_base = smem_u32(smem);

    const int tid = threadIdx.x;
    const int wid = tid >> 5;
    const int lane = tid & 31;
    const int wm = wid >> 1;            // 0..3  (32-row slab)
    const int wn = wid & 1;             // 0..1  (64-col slab)
    const int lrow = lane & 15;         // ldmatrix row select
    const int lcol = (lane >> 4) * 8;   // ldmatrix k-half select

    const __half* A = args.A + (long long)bb * args.strideA;
    const __half* B = args.B + (long long)bb * args.strideB;

    const int Keff = args.kmax_mode ? min(args.K, (by + 1) * BM) : args.K;
    const int nch = Keff / BK;
    const int arow = by * BM;
    const int brow = bx * BN;

    float acc[2][8][4];
    #pragma unroll
    for (int i = 0; i < 2; i++)
        #pragma unroll
        for (int j = 0; j < 8; j++)
            #pragma unroll
            for (int k = 0; k < 4; k++) acc[i][j][k] = 0.f;

    // prologue: chunk 0 -> stage 0
    load_tile(A, arow, args.lda, 0, smem_base);
    load_tile(B, brow, args.ldb, 0, smem_base + TILE_B);
    CP_COMMIT();

    for (int c = 0; c < nch; c++) {
        const int p = c & 1;
        if (c + 1 < nch) {
            const uint32_t sq = smem_base + (p ^ 1) * STAGE_B;
            const int k0 = (c + 1) * BK;
            load_tile(A, arow, args.lda, k0, sq);
            load_tile(B, brow, args.ldb, k0, sq + TILE_B);
            CP_COMMIT();
            CP_WAIT(1);
        } else {
            CP_WAIT(0);
        }
        __syncthreads();

        const uint32_t sp = smem_base + p * STAGE_B;
        #pragma unroll
        for (int kk = 0; kk < 2; kk++) {
            const uint32_t koff = (uint32_t)(kk * 16 + lcol) * 2;
            // A fragments, 2 m16 blocks
            uint32_t af[2][4];
            #pragma unroll
            for (int mi = 0; mi < 2; mi++) {
                uint32_t ra = (uint32_t)((wm * 32 + mi * 16 + lrow) * LDSROW) * 2 + koff;
                ldmat_x4(af[mi][0], af[mi][1], af[mi][2], af[mi][3], sp + ra);
            }
            // B fragments, 8 n8 blocks (4 ldmatrix.x4)
            uint32_t b0[8], b1[8];
            #pragma unroll
            for (int np = 0; np < 4; np++) {
                uint32_t rb = (uint32_t)((wn * 64 + np * 16 + lrow) * LDSROW) * 2 + koff;
                uint32_t r0, r1, r2, r3;
                ldmat_x4(r0, r1, r2, r3, sp + TILE_B + rb);
                b0[np * 2] = r0; b1[np * 2] = r2;
                b0[np * 2 + 1] = r1; b1[np * 2 + 1] = r3;
            }
            #pragma unroll
            for (int mi = 0; mi < 2; mi++)
                #pragma unroll
                for (int j = 0; j < 8; j++)
                    mma_fp16(acc[mi][j], af[mi], b0[j], b1[j]);
        }
        __syncthreads();
    }

    // epilogue
    float* C = args.C ? args.C + (long long)bb * args.strideC : nullptr;
    __half* Ch = args.Ch ? args.Ch + (long long)bb * args.strideC : nullptr;
    const int g = lane >> 2;
    const int tig = lane & 3;

    #pragma unroll
    for (int mi = 0; mi < 2; mi++) {
        #pragma unroll
        for (int j = 0; j < 8; j++) {
            const int row0 = arow + wm * 32 + mi * 16 + g;
            const int col0 = brow + wn * 64 + j * 8 + 2 * tig;
            float v[4];
            #pragma unroll
            for (int k = 0; k < 4; k++) v[k] = acc[mi][j][k] * args.scale;
            if (args.bias) {
                v[0] += args.bias[col0];     v[1] += args.bias[col0 + 1];
                v[2] += args.bias[col0];     v[3] += args.bias[col0 + 1];
            }
            const long long o0 = (long long)row0 * args.ldc + col0;
            const long long o1 = (long long)(row0 + 8) * args.ldc + col0;
            if (C) {
                C[o0] = v[0]; C[o0 + 1] = v[1];
                C[o1] = v[2]; C[o1 + 1] = v[3];
            }
            if (Ch) {
                *(__half2*)(Ch + o0) = __floats2half2_rn(v[0], v[1]);
                *(__half2*)(Ch + o1) = __floats2half2_rn(v[2], v[3]);
            }
        }
    }
}

// ---------------------------------------------------------------------------
// Causal row softmax: fp32 sim -> fp16 probs, zero-filled to 128-block edge
// ---------------------------------------------------------------------------
__global__ void __launch_bounds__(256)
softmax_kernel(const float* __restrict__ sim, __half* __restrict__ ph)
{
    const int i = blockIdx.x;
    const int b = blockIdx.y;
    const float* row = sim + ((size_t)b * S_ + i) * S_;
    __half* rh = ph + ((size_t)b * S_ + i) * S_;
    const int n = i + 1;

    __shared__ float red[256];
    const int t = threadIdx.x;

    float m = -FLT_MAX;
    for (int j = t; j < n; j += 256) m = fmaxf(m, row[j]);
    red[t] = m; __syncthreads();
    for (int s = 128; s > 0; s >>= 1) {
        if (t < s) red[t] = fmaxf(red[t], red[t + s]);
        __syncthreads();
    }
    m = red[0]; __syncthreads();

    float sum = 0.f;
    for (int j = t; j < n; j += 256) sum += expf(row[j] - m);
    red[t] = sum; __syncthreads();
    for (int s = 128; s > 0; s >>= 1) {
        if (t < s) red[t] += red[t + s];
        __syncthreads();
    }
    const float inv = 1.f / red[0];
    __syncthreads();

    for (int j = t; j < n; j += 256)
        rh[j] = __float2half(expf(row[j] - m) * inv);
    const int pad_end = min(S_, ((n + BM - 1) / BM) * BM);
    for (int j = n + t; j < pad_end; j += 256)
        rh[j] = __float2half(0.f);
}

// ---------------------------------------------------------------------------
// Launch
// ---------------------------------------------------------------------------
static void* sym(const void* s) { void* p; cudaGetSymbolAddress(&p, s); return p; }

extern "C" void kernel_launch(void* const* d_in, const int* in_sizes, int n_in,
                              void* d_out, int out_size)
{
    const float* x     = (const float*)d_in[0];
    const float* w_qkv = (const float*)d_in[1];
    const float* w_out = (const float*)d_in[2];
    const float* b_out = (const float*)d_in[3];
    float* out = (float*)d_out;

    float* qkv  = (float*)sym(g_qkv);
    float* simP = (float*)sym(g_sim);
    __half* xh    = (__half*)sym(g_xh);
    __half* wqt   = (__half*)sym(g_wqkvt);
    __half* wot   = (__half*)sym(g_woutt);
    __half* qkvh  = (__half*)sym(g_qkvh);
    __half* vt    = (__half*)sym(g_vt);
    __half* attn  = (__half*)sym(g_attn);
    __half* inner = (__half*)sym(g_inner);

    cudaFuncSetAttribute(gemm_mma_kernel,
                         cudaFuncAttributeMaxDynamicSharedMemorySize, SMEM_TOTAL);

    const float scale = 1.0f / 32.0f;   // DIM_INNER^-0.5

    // 1) input conversion / weight transposes
    cvt_rm_kernel<<<2048, 256>>>((const float4*)x, (__half2*)xh,
                                 (long long)M1 * DIN / 4);
    cvt_tr_kernel<<<dim3(N1 / 32, DIN / 32, 1), dim3(32, 8)>>>(
        w_qkv, wqt, N1, DIN, 0, 0);
    cvt_tr_kernel<<<dim3(DOUT / 32, DINNER / 32, 1), dim3(32, 8)>>>(
        w_out, wot, DOUT, DINNER, 0, 0);

    // 2) QKV projection -> fp32 qkv + fp16 qkvh (fused)
    {
        GemmArgs a = { xh, wqt, qkv, qkvh, nullptr,
                       DIN, DIN, DIN, N1, 0, 0, 0, 1.0f, 0, 0 };
        gemm_mma_kernel<<<dim3(N1 / BN, M1 / BM, 1), NTH, SMEM_TOTAL>>>(a);
    }

    // 3) V transpose (per batch), fp32 qkv -> fp16 V^T
    cvt_tr_kernel<<<dim3(DINNER / 32, S_ / 32, B_), dim3(32, 8)>>>(
        qkv + 2 * DINNER, vt, N1, S_,
        (long long)S_ * N1, (long long)DINNER * S_);

    // 4) sim = scale * Q K^T (causal blocks only), fp32
    {
        GemmArgs a = { qkvh, qkvh + DINNER, simP, nullptr, nullptr,
                       DINNER, N1, N1, S_,
                       (long long)S_ * N1, (long long)S_ * N1, (long long)S_ * S_,
                       scale, 1, 0 };
        gemm_mma_kernel<<<dim3(S_ / BN, S_ / BM, B_), NTH, SMEM_TOTAL>>>(a);
    }

    // 5) softmax -> fp16 probs (fused)
    softmax_kernel<<<dim3(S_, B_), 256>>>(simP, attn);

    // 6) inner = attn @ V -> fp16 only (fused, causal K-limit)
    {
        GemmArgs a = { attn, vt, nullptr, inner, nullptr,
                       S_, S_, S_, DINNER,
                       (long long)S_ * S_, (long long)DINNER * S_,
                       (long long)S_ * DINNER,
                       1.0f, 0, 1 };
        gemm_mma_kernel<<<dim3(DINNER / BN, S_ / BM, B_), NTH, SMEM_TOTAL>>>(a);
    }

    // 7) out = inner @ W_out + b_out (fp32)
    {
        GemmArgs a = { inner, wot, out, nullptr, b_out,
                       DINNER, DINNER, DINNER, DOUT, 0, 0, 0, 1.0f, 0, 0 };
        gemm_mma_kernel<<<dim3(DOUT / BN, M1 / BM, 1), NTH, SMEM_TOTAL>>>(a);
    }
}

// round 8
// speedup vs baseline: 5.2982x; 1.5661x over previous
#include <cuda_runtime.h>
#include <cuda_fp16.h>
#include <cstdint>
#include <float.h>

// ---------------------------------------------------------------------------
// Problem constants
// ---------------------------------------------------------------------------
#define B_     4
#define S_     2048
#define DIN    1024
#define DINNER 1024
#define DOUT   1024
#define M1     (B_ * S_)        // 8192
#define N1     (3 * DINNER)     // 3072

// GEMM tile config (mma.sync)
#define BM 128
#define BN 128
#define BK 32
#define NTH 256                 // 8 warps: 4 (m) x 2 (n)
#define PAD 8
#define LDSROW (BK + PAD)       // 40 fp16 per smem row (80 B)
#define TILE_B (BM * LDSROW * 2)    // 10240 bytes per tile
#define STAGE_B (2 * TILE_B)        // A, B = 20480
#define NSTAGE 3
#define SMEM_TOTAL (NSTAGE * STAGE_B)   // 61440

// ---------------------------------------------------------------------------
// PTX helpers (all baseline-PTX legal on compute_103)
// ---------------------------------------------------------------------------
__device__ __forceinline__ uint32_t smem_u32(const void* p) {
    uint32_t a;
    asm("{ .reg .u64 t; cvta.to.shared.u64 t, %1; cvt.u32.u64 %0, t; }"
        : "=r"(a) : "l"(p));
    return a;
}

__device__ __forceinline__ void cp_async16(uint32_t dst, const void* src) {
    asm volatile("cp.async.cg.shared.global [%0], [%1], 16;"
                 :: "r"(dst), "l"(src));
}
#define CP_COMMIT() asm volatile("cp.async.commit_group;" ::: "memory")
#define CP_WAIT(n)  asm volatile("cp.async.wait_group %0;" :: "n"(n) : "memory")

__device__ __forceinline__ void ldmat_x4(uint32_t& r0, uint32_t& r1,
                                         uint32_t& r2, uint32_t& r3,
                                         uint32_t addr) {
    asm volatile("ldmatrix.sync.aligned.m8n8.x4.shared.b16 {%0,%1,%2,%3}, [%4];"
                 : "=r"(r0), "=r"(r1), "=r"(r2), "=r"(r3) : "r"(addr));
}

__device__ __forceinline__ void mma_fp16(float* c, const uint32_t* a,
                                         uint32_t b0, uint32_t b1) {
    asm volatile(
        "mma.sync.aligned.m16n8k16.row.col.f32.f16.f16.f32 "
        "{%0,%1,%2,%3}, {%4,%5,%6,%7}, {%8,%9}, {%0,%1,%2,%3};"
        : "+f"(c[0]), "+f"(c[1]), "+f"(c[2]), "+f"(c[3])
        : "r"(a[0]), "r"(a[1]), "r"(a[2]), "r"(a[3]), "r"(b0), "r"(b1));
}

// ---------------------------------------------------------------------------
// Scratch (static device globals)
// ---------------------------------------------------------------------------
__device__ float g_qkv[(size_t)M1 * N1];                 // 96 MB fp32
__device__ float g_sim[(size_t)B_ * S_ * S_];            // 64 MB fp32

__device__ __half g_xh[(size_t)M1 * DIN];                // 16 MB
__device__ __half g_wqkvt[(size_t)N1 * DIN];             // 6 MB (transposed)
__device__ __half g_woutt[(size_t)DOUT * DINNER];        // 2 MB (transposed)
__device__ __half g_qkvh[(size_t)M1 * N1];               // 48 MB
__device__ __half g_vt[(size_t)B_ * DINNER * S_];        // 16 MB (V^T per batch)
__device__ __half g_attn[(size_t)B_ * S_ * S_];          // 32 MB
__device__ __half g_inner[(size_t)M1 * DINNER];          // 16 MB

// ---------------------------------------------------------------------------
// Conversion kernels
// ---------------------------------------------------------------------------
__global__ void cvt_rm_kernel(const float4* __restrict__ src,
                              __half2* __restrict__ h, long long n4) {
    long long i = (long long)blockIdx.x * blockDim.x + threadIdx.x;
    long long stride = (long long)gridDim.x * blockDim.x;
    for (; i < n4; i += stride) {
        float4 v = src[i];
        h[2 * i]     = __floats2half2_rn(v.x, v.y);
        h[2 * i + 1] = __floats2half2_rn(v.z, v.w);
    }
}

// fp32 [R,C] (row stride sld) -> transposed fp16 [C,R] (row stride dld)
__global__ void cvt_tr_kernel(const float* __restrict__ src,
                              __half* __restrict__ h,
                              int sld, int dld,
                              long long sbatch, long long dbatch) {
    __shared__ float t[32][33];
    const int c0 = blockIdx.x * 32;
    const int r0 = blockIdx.y * 32;
    const long long sb = (long long)blockIdx.z * sbatch;
    const long long db = (long long)blockIdx.z * dbatch;
    const int tx = threadIdx.x, ty = threadIdx.y;

    #pragma unroll
    for (int i = 0; i < 32; i += 8)
        t[ty + i][tx] = src[sb + (long long)(r0 + ty + i) * sld + c0 + tx];
    __syncthreads();
    #pragma unroll
    for (int i = 0; i < 32; i += 8) {
        long long o = db + (long long)(c0 + ty + i) * dld + r0 + tx;
        h[o] = __float2half(t[tx][ty + i]);
    }
}

// ---------------------------------------------------------------------------
// mma.sync fp16 GEMM: C[M,N] = scale * sum_k A[m,k]*B[n,k] (+bias)
// A: [M,K] K-contiguous ; B: [N,K] K-contiguous
// 3-stage cp.async pipeline, one __syncthreads per K-chunk.
// ---------------------------------------------------------------------------
struct GemmArgs {
    const __half *A, *B;
    float* C;                    // nullable fp32 out
    __half* Ch;                  // nullable fp16 out
    const float* bias;           // nullable
    int K, lda, ldb, ldc;
    long long strideA, strideB, strideC;
    float scale;
    int causal_skip;             // skip CTA if bx > by
    int kmax_mode;               // K_eff = min(K, (by+1)*BM)
};

__device__ __forceinline__ void load_tile(const __half* __restrict__ g,
                                          int row0, int ld, int k0, uint32_t sm) {
    const int tid = threadIdx.x;
    #pragma unroll
    for (int t = 0; t < 2; t++) {
        int idx = t * NTH + tid;        // 0..511
        int r  = idx >> 2;              // 0..127
        int kc = (idx & 3) * 8;         // 0,8,16,24
        cp_async16(sm + (uint32_t)(r * LDSROW + kc) * 2,
                   g + (long long)(row0 + r) * ld + k0 + kc);
    }
}

__global__ void __launch_bounds__(NTH, 2)
gemm_mma_kernel(GemmArgs args)
{
    const int bx = blockIdx.x, by = blockIdx.y, bb = blockIdx.z;
    if (args.causal_skip && bx > by) return;

    extern __shared__ char smem[];
    const uint32_t smem_base = smem_u32(smem);

    const int tid = threadIdx.x;
    const int wid = tid >> 5;
    const int lane = tid & 31;
    const int wm = wid >> 1;            // 0..3  (32-row slab)
    const int wn = wid & 1;             // 0..1  (64-col slab)
    const int lrow = lane & 15;         // ldmatrix row select
    const int lcol = (lane >> 4) * 8;   // ldmatrix k-half select

    const __half* A = args.A + (long long)bb * args.strideA;
    const __half* B = args.B + (long long)bb * args.strideB;

    const int Keff = args.kmax_mode ? min(args.K, (by + 1) * BM) : args.K;
    const int nch = Keff / BK;
    const int arow = by * BM;
    const int brow = bx * BN;

    float acc[2][8][4];
    #pragma unroll
    for (int i = 0; i < 2; i++)
        #pragma unroll
        for (int j = 0; j < 8; j++)
            #pragma unroll
            for (int k = 0; k < 4; k++) acc[i][j][k] = 0.f;

    // prologue: chunks 0,1 -> stages 0,1
    load_tile(A, arow, args.lda, 0, smem_base);
    load_tile(B, brow, args.ldb, 0, smem_base + TILE_B);
    CP_COMMIT();
    if (nch > 1) {
        load_tile(A, arow, args.lda, BK, smem_base + STAGE_B);
        load_tile(B, brow, args.ldb, BK, smem_base + STAGE_B + TILE_B);
        CP_COMMIT();
    }

    for (int c = 0; c < nch; c++) {
        // wait for chunk c's group (outstanding allowed: 1 mid-stream, 0 at tail)
        if (c < nch - 1) { CP_WAIT(1); } else { CP_WAIT(0); }
        __syncthreads();   // publishes chunk c; protects stage (c+2)%3 for reuse

        // prefetch chunk c+2 into stage (c+2)%3
        if (c + 2 < nch) {
            const uint32_t sq = smem_base + ((c + 2) % NSTAGE) * STAGE_B;
            const int k0 = (c + 2) * BK;
            load_tile(A, arow, args.lda, k0, sq);
            load_tile(B, brow, args.ldb, k0, sq + TILE_B);
            CP_COMMIT();
        }

        const uint32_t sp = smem_base + (c % NSTAGE) * STAGE_B;
        #pragma unroll
        for (int kk = 0; kk < 2; kk++) {
            const uint32_t koff = (uint32_t)(kk * 16 + lcol) * 2;
            // A fragments, 2 m16 blocks
            uint32_t af[2][4];
            #pragma unroll
            for (int mi = 0; mi < 2; mi++) {
                uint32_t ra = (uint32_t)((wm * 32 + mi * 16 + lrow) * LDSROW) * 2 + koff;
                ldmat_x4(af[mi][0], af[mi][1], af[mi][2], af[mi][3], sp + ra);
            }
            // B fragments, 8 n8 blocks (4 ldmatrix.x4)
            uint32_t b0[8], b1[8];
            #pragma unroll
            for (int np = 0; np < 4; np++) {
                uint32_t rb = (uint32_t)((wn * 64 + np * 16 + lrow) * LDSROW) * 2 + koff;
                uint32_t r0, r1, r2, r3;
                ldmat_x4(r0, r1, r2, r3, sp + TILE_B + rb);
                b0[np * 2] = r0; b1[np * 2] = r2;
                b0[np * 2 + 1] = r1; b1[np * 2 + 1] = r3;
            }
            #pragma unroll
            for (int mi = 0; mi < 2; mi++)
                #pragma unroll
                for (int j = 0; j < 8; j++)
                    mma_fp16(acc[mi][j], af[mi], b0[j], b1[j]);
        }
    }

    // epilogue (acc is thread-private; no sync needed)
    float* C = args.C ? args.C + (long long)bb * args.strideC : nullptr;
    __half* Ch = args.Ch ? args.Ch + (long long)bb * args.strideC : nullptr;
    const int g = lane >> 2;
    const int tig = lane & 3;

    #pragma unroll
    for (int mi = 0; mi < 2; mi++) {
        #pragma unroll
        for (int j = 0; j < 8; j++) {
            const int row0 = arow + wm * 32 + mi * 16 + g;
            const int col0 = brow + wn * 64 + j * 8 + 2 * tig;
            float v[4];
            #pragma unroll
            for (int k = 0; k < 4; k++) v[k] = acc[mi][j][k] * args.scale;
            if (args.bias) {
                v[0] += args.bias[col0];     v[1] += args.bias[col0 + 1];
                v[2] += args.bias[col0];     v[3] += args.bias[col0 + 1];
            }
            const long long o0 = (long long)row0 * args.ldc + col0;
            const long long o1 = (long long)(row0 + 8) * args.ldc + col0;
            if (C) {
                C[o0] = v[0]; C[o0 + 1] = v[1];
                C[o1] = v[2]; C[o1 + 1] = v[3];
            }
            if (Ch) {
                *(__half2*)(Ch + o0) = __floats2half2_rn(v[0], v[1]);
                *(__half2*)(Ch + o1) = __floats2half2_rn(v[2], v[3]);
            }
        }
    }
}

// ---------------------------------------------------------------------------
// Causal row softmax: fp32 sim -> fp16 probs, zero-filled to 128-block edge
// ---------------------------------------------------------------------------
__global__ void __launch_bounds__(256)
softmax_kernel(const float* __restrict__ sim, __half* __restrict__ ph)
{
    const int i = blockIdx.x;
    const int b = blockIdx.y;
    const float* row = sim + ((size_t)b * S_ + i) * S_;
    __half* rh = ph + ((size_t)b * S_ + i) * S_;
    const int n = i + 1;

    __shared__ float red[256];
    const int t = threadIdx.x;

    float m = -FLT_MAX;
    for (int j = t; j < n; j += 256) m = fmaxf(m, row[j]);
    red[t] = m; __syncthreads();
    for (int s = 128; s > 0; s >>= 1) {
        if (t < s) red[t] = fmaxf(red[t], red[t + s]);
        __syncthreads();
    }
    m = red[0]; __syncthreads();

    float sum = 0.f;
    for (int j = t; j < n; j += 256) sum += expf(row[j] - m);
    red[t] = sum; __syncthreads();
    for (int s = 128; s > 0; s >>= 1) {
        if (t < s) red[t] += red[t + s];
        __syncthreads();
    }
    const float inv = 1.f / red[0];
    __syncthreads();

    for (int j = t; j < n; j += 256)
        rh[j] = __float2half(expf(row[j] - m) * inv);
    const int pad_end = min(S_, ((n + BM - 1) / BM) * BM);
    for (int j = n + t; j < pad_end; j += 256)
        rh[j] = __float2half(0.f);
}

// ---------------------------------------------------------------------------
// Launch
// ---------------------------------------------------------------------------
static void* sym(const void* s) { void* p; cudaGetSymbolAddress(&p, s); return p; }

extern "C" void kernel_launch(void* const* d_in, const int* in_sizes, int n_in,
                              void* d_out, int out_size)
{
    const float* x     = (const float*)d_in[0];
    const float* w_qkv = (const float*)d_in[1];
    const float* w_out = (const float*)d_in[2];
    const float* b_out = (const float*)d_in[3];
    float* out = (float*)d_out;

    float* qkv  = (float*)sym(g_qkv);
    float* simP = (float*)sym(g_sim);
    __half* xh    = (__half*)sym(g_xh);
    __half* wqt   = (__half*)sym(g_wqkvt);
    __half* wot   = (__half*)sym(g_woutt);
    __half* qkvh  = (__half*)sym(g_qkvh);
    __half* vt    = (__half*)sym(g_vt);
    __half* attn  = (__half*)sym(g_attn);
    __half* inner = (__half*)sym(g_inner);

    cudaFuncSetAttribute(gemm_mma_kernel,
                         cudaFuncAttributeMaxDynamicSharedMemorySize, SMEM_TOTAL);

    const float scale = 1.0f / 32.0f;   // DIM_INNER^-0.5

    // 1) input conversion / weight transposes
    cvt_rm_kernel<<<2048, 256>>>((const float4*)x, (__half2*)xh,
                                 (long long)M1 * DIN / 4);
    cvt_tr_kernel<<<dim3(N1 / 32, DIN / 32, 1), dim3(32, 8)>>>(
        w_qkv, wqt, N1, DIN, 0, 0);
    cvt_tr_kernel<<<dim3(DOUT / 32, DINNER / 32, 1), dim3(32, 8)>>>(
        w_out, wot, DOUT, DINNER, 0, 0);

    // 2) QKV projection -> fp32 qkv + fp16 qkvh (fused)
    {
        GemmArgs a = { xh, wqt, qkv, qkvh, nullptr,
                       DIN, DIN, DIN, N1, 0, 0, 0, 1.0f, 0, 0 };
        gemm_mma_kernel<<<dim3(N1 / BN, M1 / BM, 1), NTH, SMEM_TOTAL>>>(a);
    }

    // 3) V transpose (per batch), fp32 qkv -> fp16 V^T
    cvt_tr_kernel<<<dim3(DINNER / 32, S_ / 32, B_), dim3(32, 8)>>>(
        qkv + 2 * DINNER, vt, N1, S_,
        (long long)S_ * N1, (long long)DINNER * S_);

    // 4) sim = scale * Q K^T (causal blocks only), fp32
    {
        GemmArgs a = { qkvh, qkvh + DINNER, simP, nullptr, nullptr,
                       DINNER, N1, N1, S_,
                       (long long)S_ * N1, (long long)S_ * N1, (long long)S_ * S_,
                       scale, 1, 0 };
        gemm_mma_kernel<<<dim3(S_ / BN, S_ / BM, B_), NTH, SMEM_TOTAL>>>(a);
    }

    // 5) softmax -> fp16 probs (fused)
    softmax_kernel<<<dim3(S_, B_), 256>>>(simP, attn);

    // 6) inner = attn @ V -> fp16 only (fused, causal K-limit)
    {
        GemmArgs a = { attn, vt, nullptr, inner, nullptr,
                       S_, S_, S_, DINNER,
                       (long long)S_ * S_, (long long)DINNER * S_,
                       (long long)S_ * DINNER,
                       1.0f, 0, 1 };
        gemm_mma_kernel<<<dim3(DINNER / BN, S_ / BM, B_), NTH, SMEM_TOTAL>>>(a);
    }

    // 7) out = inner @ W_out + b_out (fp32)
    {
        GemmArgs a = { inner, wot, out, nullptr, b_out,
                       DINNER, DINNER, DINNER, DOUT, 0, 0, 0, 1.0f, 0, 0 };
        gemm_mma_kernel<<<dim3(DOUT / BN, M1 / BM, 1), NTH, SMEM_TOTAL>>>(a);
    }
}

// round 9
// speedup vs baseline: 5.8385x; 1.1020x over previous
#include <cuda_runtime.h>
#include <cuda_fp16.h>
#include <cstdint>
#include <float.h>

// ---------------------------------------------------------------------------
// Problem constants
// ---------------------------------------------------------------------------
#define B_     4
#define S_     2048
#define DIN    1024
#define DINNER 1024
#define DOUT   1024
#define M1     (B_ * S_)        // 8192
#define N1     (3 * DINNER)     // 3072

// GEMM tile config (mma.sync)
#define BM 128
#define BN 128
#define BK 64
#define NTH 256                 // 8 warps: 4 (m) x 2 (n)
#define PAD 8
#define LDSROW (BK + PAD)       // 72 fp16 per smem row (144 B)
#define TILE_B (BM * LDSROW * 2)    // 18432 bytes per tile
#define STAGE_B (2 * TILE_B)        // A, B = 36864
#define NSTAGE 2
#define SMEM_TOTAL (NSTAGE * STAGE_B)   // 73728

// ---------------------------------------------------------------------------
// PTX helpers (all baseline-PTX legal on compute_103)
// ---------------------------------------------------------------------------
__device__ __forceinline__ uint32_t smem_u32(const void* p) {
    uint32_t a;
    asm("{ .reg .u64 t; cvta.to.shared.u64 t, %1; cvt.u32.u64 %0, t; }"
        : "=r"(a) : "l"(p));
    return a;
}

__device__ __forceinline__ void cp_async16(uint32_t dst, const void* src) {
    asm volatile("cp.async.cg.shared.global [%0], [%1], 16;"
                 :: "r"(dst), "l"(src));
}
#define CP_COMMIT() asm volatile("cp.async.commit_group;" ::: "memory")
#define CP_WAIT(n)  asm volatile("cp.async.wait_group %0;" :: "n"(n) : "memory")

__device__ __forceinline__ void ldmat_x4(uint32_t& r0, uint32_t& r1,
                                         uint32_t& r2, uint32_t& r3,
                                         uint32_t addr) {
    asm volatile("ldmatrix.sync.aligned.m8n8.x4.shared.b16 {%0,%1,%2,%3}, [%4];"
                 : "=r"(r0), "=r"(r1), "=r"(r2), "=r"(r3) : "r"(addr));
}

__device__ __forceinline__ void mma_fp16(float* c, const uint32_t* a,
                                         uint32_t b0, uint32_t b1) {
    asm volatile(
        "mma.sync.aligned.m16n8k16.row.col.f32.f16.f16.f32 "
        "{%0,%1,%2,%3}, {%4,%5,%6,%7}, {%8,%9}, {%0,%1,%2,%3};"
        : "+f"(c[0]), "+f"(c[1]), "+f"(c[2]), "+f"(c[3])
        : "r"(a[0]), "r"(a[1]), "r"(a[2]), "r"(a[3]), "r"(b0), "r"(b1));
}

// ---------------------------------------------------------------------------
// Scratch (static device globals)
// ---------------------------------------------------------------------------
__device__ float g_qkv[(size_t)M1 * N1];                 // 96 MB fp32
__device__ float g_sim[(size_t)B_ * S_ * S_];            // 64 MB fp32

__device__ __half g_xh[(size_t)M1 * DIN];                // 16 MB
__device__ __half g_wqkvt[(size_t)N1 * DIN];             // 6 MB (transposed)
__device__ __half g_woutt[(size_t)DOUT * DINNER];        // 2 MB (transposed)
__device__ __half g_qkvh[(size_t)M1 * N1];               // 48 MB
__device__ __half g_vt[(size_t)B_ * DINNER * S_];        // 16 MB (V^T per batch)
__device__ __half g_attn[(size_t)B_ * S_ * S_];          // 32 MB
__device__ __half g_inner[(size_t)M1 * DINNER];          // 16 MB

// ---------------------------------------------------------------------------
// Conversion kernels
// ---------------------------------------------------------------------------
__global__ void cvt_rm_kernel(const float4* __restrict__ src,
                              __half2* __restrict__ h, long long n4) {
    long long i = (long long)blockIdx.x * blockDim.x + threadIdx.x;
    long long stride = (long long)gridDim.x * blockDim.x;
    for (; i < n4; i += stride) {
        float4 v = src[i];
        h[2 * i]     = __floats2half2_rn(v.x, v.y);
        h[2 * i + 1] = __floats2half2_rn(v.z, v.w);
    }
}

// fp32 [R,C] (row stride sld) -> transposed fp16 [C,R] (row stride dld)
__global__ void cvt_tr_kernel(const float* __restrict__ src,
                              __half* __restrict__ h,
                              int sld, int dld,
                              long long sbatch, long long dbatch) {
    __shared__ float t[32][33];
    const int c0 = blockIdx.x * 32;
    const int r0 = blockIdx.y * 32;
    const long long sb = (long long)blockIdx.z * sbatch;
    const long long db = (long long)blockIdx.z * dbatch;
    const int tx = threadIdx.x, ty = threadIdx.y;

    #pragma unroll
    for (int i = 0; i < 32; i += 8)
        t[ty + i][tx] = src[sb + (long long)(r0 + ty + i) * sld + c0 + tx];
    __syncthreads();
    #pragma unroll
    for (int i = 0; i < 32; i += 8) {
        long long o = db + (long long)(c0 + ty + i) * dld + r0 + tx;
        h[o] = __float2half(t[tx][ty + i]);
    }
}

// ---------------------------------------------------------------------------
// mma.sync fp16 GEMM: C[M,N] = scale * sum_k A[m,k]*B[n,k] (+bias)
// A: [M,K] K-contiguous ; B: [N,K] K-contiguous
// BK=64, 2-stage cp.async ring, 1 barrier/chunk, software-pipelined fragments.
// ---------------------------------------------------------------------------
struct GemmArgs {
    const __half *A, *B;
    float* C;                    // nullable fp32 out
    __half* Ch;                  // nullable fp16 out
    const float* bias;           // nullable
    int K, lda, ldb, ldc;
    long long strideA, strideB, strideC;
    float scale;
    int causal_skip;             // skip CTA if bx > by
    int kmax_mode;               // K_eff = min(K, (by+1)*BM)
};

__device__ __forceinline__ void load_tile(const __half* __restrict__ g,
                                          int row0, int ld, int k0, uint32_t sm) {
    const int tid = threadIdx.x;
    #pragma unroll
    for (int t = 0; t < 4; t++) {
        int idx = t * NTH + tid;        // 0..1023
        int r  = idx >> 3;              // 0..127
        int kc = (idx & 7) * 8;         // 0..56
        cp_async16(sm + (uint32_t)(r * LDSROW + kc) * 2,
                   g + (long long)(row0 + r) * ld + k0 + kc);
    }
}

__global__ void __launch_bounds__(NTH, 2)
gemm_mma_kernel(GemmArgs args)
{
    const int bx = blockIdx.x, by = blockIdx.y, bb = blockIdx.z;
    if (args.causal_skip && bx > by) return;

    extern __shared__ char smem[];
    const uint32_t smem_base = smem_u32(smem);

    const int tid = threadIdx.x;
    const int wid = tid >> 5;
    const int lane = tid & 31;
    const int wm = wid >> 1;            // 0..3  (32-row slab)
    const int wn = wid & 1;             // 0..1  (64-col slab)
    const int lrow = lane & 15;         // ldmatrix row select
    const int lcol = (lane >> 4) * 8;   // ldmatrix k-half select

    const __half* A = args.A + (long long)bb * args.strideA;
    const __half* B = args.B + (long long)bb * args.strideB;

    const int Keff = args.kmax_mode ? min(args.K, (by + 1) * BM) : args.K;
    const int nch = Keff / BK;
    const int arow = by * BM;
    const int brow = bx * BN;

    float acc[2][8][4];
    #pragma unroll
    for (int i = 0; i < 2; i++)
        #pragma unroll
        for (int j = 0; j < 8; j++)
            #pragma unroll
            for (int k = 0; k < 4; k++) acc[i][j][k] = 0.f;

    // prologue: chunk 0 -> stage 0
    load_tile(A, arow, args.lda, 0, smem_base);
    load_tile(B, brow, args.ldb, 0, smem_base + TILE_B);
    CP_COMMIT();

    // per-warp base offsets (loop-invariant)
    const uint32_t a_off0 = (uint32_t)((wm * 32 + lrow) * LDSROW) * 2 + lcol * 2;
    const uint32_t b_off0 = (uint32_t)((wn * 64 + lrow) * LDSROW) * 2 + lcol * 2;

    for (int c = 0; c < nch; c++) {
        CP_WAIT(0);          // chunk c resident
        __syncthreads();     // publish chunk c; stage c^1 free for overwrite

        // prefetch chunk c+1 into the other stage
        if (c + 1 < nch) {
            const uint32_t sq = smem_base + ((c + 1) & 1) * STAGE_B;
            const int k0 = (c + 1) * BK;
            load_tile(A, arow, args.lda, k0, sq);
            load_tile(B, brow, args.ldb, k0, sq + TILE_B);
            CP_COMMIT();
        }

        const uint32_t sp = smem_base + (c & 1) * STAGE_B;
        const uint32_t a_base = sp + a_off0;
        const uint32_t b_base = sp + TILE_B + b_off0;

        // ---- software-pipelined 8 phases: (kk 0..3) x (jg 0..1) ----
        uint32_t Abuf[2][8];   // [buf][mi*4 + r]
        uint32_t Bbuf[2][8];   // [buf][b0 x4, b1 x4]

        // preload phase 0 fragments: A(kk=0), B(kk=0, jg=0)
        {
            ldmat_x4(Abuf[0][0], Abuf[0][1], Abuf[0][2], Abuf[0][3], a_base);
            ldmat_x4(Abuf[0][4], Abuf[0][5], Abuf[0][6], Abuf[0][7],
                     a_base + (uint32_t)(16 * LDSROW) * 2);
            #pragma unroll
            for (int np = 0; np < 2; np++) {
                uint32_t r0, r1, r2, r3;
                ldmat_x4(r0, r1, r2, r3,
                         b_base + (uint32_t)(np * 16 * LDSROW) * 2);
                Bbuf[0][np * 2]     = r0; Bbuf[0][4 + np * 2]     = r2;
                Bbuf[0][np * 2 + 1] = r1; Bbuf[0][4 + np * 2 + 1] = r3;
            }
        }

        #pragma unroll
        for (int ph = 0; ph < 8; ph++) {
            const int kk = ph >> 1;
            const int jg = ph & 1;
            const int ab = kk & 1;
            const int bbuf = ph & 1;

            // prefetch next phase's fragments
            if (ph < 7) {
                const int nkk = (ph + 1) >> 1;
                const int njg = (ph + 1) & 1;
                const uint32_t nkoff = (uint32_t)(nkk * 16) * 2;
                if (njg == 0) {   // new kk: load A(nkk)
                    const int nab = nkk & 1;
                    ldmat_x4(Abuf[nab][0], Abuf[nab][1], Abuf[nab][2], Abuf[nab][3],
                             a_base + nkoff);
                    ldmat_x4(Abuf[nab][4], Abuf[nab][5], Abuf[nab][6], Abuf[nab][7],
                             a_base + (uint32_t)(16 * LDSROW) * 2 + nkoff);
                }
                const int nbb = (ph + 1) & 1;
                #pragma unroll
                for (int np = 0; np < 2; np++) {
                    uint32_t r0, r1, r2, r3;
                    ldmat_x4(r0, r1, r2, r3,
                             b_base + (uint32_t)((njg * 2 + np) * 16 * LDSROW) * 2
                                    + nkoff);
                    Bbuf[nbb][np * 2]     = r0; Bbuf[nbb][4 + np * 2]     = r2;
                    Bbuf[nbb][np * 2 + 1] = r1; Bbuf[nbb][4 + np * 2 + 1] = r3;
                }
            }

            // 8 MMAs for this phase
            #pragma unroll
            for (int mi = 0; mi < 2; mi++)
                #pragma unroll
                for (int jl = 0; jl < 4; jl++)
                    mma_fp16(acc[mi][jg * 4 + jl], &Abuf[ab][mi * 4],
                             Bbuf[bbuf][jl], Bbuf[bbuf][4 + jl]);
        }
    }

    // epilogue (acc is thread-private; no sync needed)
    float* C = args.C ? args.C + (long long)bb * args.strideC : nullptr;
    __half* Ch = args.Ch ? args.Ch + (long long)bb * args.strideC : nullptr;
    const int g = lane >> 2;
    const int tig = lane & 3;

    #pragma unroll
    for (int mi = 0; mi < 2; mi++) {
        #pragma unroll
        for (int j = 0; j < 8; j++) {
            const int row0 = arow + wm * 32 + mi * 16 + g;
            const int col0 = brow + wn * 64 + j * 8 + 2 * tig;
            float v[4];
            #pragma unroll
            for (int k = 0; k < 4; k++) v[k] = acc[mi][j][k] * args.scale;
            if (args.bias) {
                v[0] += args.bias[col0];     v[1] += args.bias[col0 + 1];
                v[2] += args.bias[col0];     v[3] += args.bias[col0 + 1];
            }
            const long long o0 = (long long)row0 * args.ldc + col0;
            const long long o1 = (long long)(row0 + 8) * args.ldc + col0;
            if (C) {
                C[o0] = v[0]; C[o0 + 1] = v[1];
                C[o1] = v[2]; C[o1 + 1] = v[3];
            }
            if (Ch) {
                *(__half2*)(Ch + o0) = __floats2half2_rn(v[0], v[1]);
                *(__half2*)(Ch + o1) = __floats2half2_rn(v[2], v[3]);
            }
        }
    }
}

// ---------------------------------------------------------------------------
// Causal row softmax: fp32 sim -> fp16 probs, zero-filled to 128-block edge
// ---------------------------------------------------------------------------
__global__ void __launch_bounds__(256)
softmax_kernel(const float* __restrict__ sim, __half* __restrict__ ph)
{
    const int i = blockIdx.x;
    const int b = blockIdx.y;
    const float* row = sim + ((size_t)b * S_ + i) * S_;
    __half* rh = ph + ((size_t)b * S_ + i) * S_;
    const int n = i + 1;

    __shared__ float red[256];
    const int t = threadIdx.x;

    float m = -FLT_MAX;
    for (int j = t; j < n; j += 256) m = fmaxf(m, row[j]);
    red[t] = m; __syncthreads();
    for (int s = 128; s > 0; s >>= 1) {
        if (t < s) red[t] = fmaxf(red[t], red[t + s]);
        __syncthreads();
    }
    m = red[0]; __syncthreads();

    float sum = 0.f;
    for (int j = t; j < n; j += 256) sum += expf(row[j] - m);
    red[t] = sum; __syncthreads();
    for (int s = 128; s > 0; s >>= 1) {
        if (t < s) red[t] += red[t + s];
        __syncthreads();
    }
    const float inv = 1.f / red[0];
    __syncthreads();

    for (int j = t; j < n; j += 256)
        rh[j] = __float2half(expf(row[j] - m) * inv);
    const int pad_end = min(S_, ((n + BM - 1) / BM) * BM);
    for (int j = n + t; j < pad_end; j += 256)
        rh[j] = __float2half(0.f);
}

// ---------------------------------------------------------------------------
// Launch
// ---------------------------------------------------------------------------
static void* sym(const void* s) { void* p; cudaGetSymbolAddress(&p, s); return p; }

extern "C" void kernel_launch(void* const* d_in, const int* in_sizes, int n_in,
                              void* d_out, int out_size)
{
    const float* x     = (const float*)d_in[0];
    const float* w_qkv = (const float*)d_in[1];
    const float* w_out = (const float*)d_in[2];
    const float* b_out = (const float*)d_in[3];
    float* out = (float*)d_out;

    float* qkv  = (float*)sym(g_qkv);
    float* simP = (float*)sym(g_sim);
    __half* xh    = (__half*)sym(g_xh);
    __half* wqt   = (__half*)sym(g_wqkvt);
    __half* wot   = (__half*)sym(g_woutt);
    __half* qkvh  = (__half*)sym(g_qkvh);
    __half* vt    = (__half*)sym(g_vt);
    __half* attn  = (__half*)sym(g_attn);
    __half* inner = (__half*)sym(g_inner);

    cudaFuncSetAttribute(gemm_mma_kernel,
                         cudaFuncAttributeMaxDynamicSharedMemorySize, SMEM_TOTAL);

    const float scale = 1.0f / 32.0f;   // DIM_INNER^-0.5

    // 1) input conversion / weight transposes
    cvt_rm_kernel<<<2048, 256>>>((const float4*)x, (__half2*)xh,
                                 (long long)M1 * DIN / 4);
    cvt_tr_kernel<<<dim3(N1 / 32, DIN / 32, 1), dim3(32, 8)>>>(
        w_qkv, wqt, N1, DIN, 0, 0);
    cvt_tr_kernel<<<dim3(DOUT / 32, DINNER / 32, 1), dim3(32, 8)>>>(
        w_out, wot, DOUT, DINNER, 0, 0);

    // 2) QKV projection -> fp32 qkv + fp16 qkvh (fused)
    {
        GemmArgs a = { xh, wqt, qkv, qkvh, nullptr,
                       DIN, DIN, DIN, N1, 0, 0, 0, 1.0f, 0, 0 };
        gemm_mma_kernel<<<dim3(N1 / BN, M1 / BM, 1), NTH, SMEM_TOTAL>>>(a);
    }

    // 3) V transpose (per batch), fp32 qkv -> fp16 V^T
    cvt_tr_kernel<<<dim3(DINNER / 32, S_ / 32, B_), dim3(32, 8)>>>(
        qkv + 2 * DINNER, vt, N1, S_,
        (long long)S_ * N1, (long long)DINNER * S_);

    // 4) sim = scale * Q K^T (causal blocks only), fp32
    {
        GemmArgs a = { qkvh, qkvh + DINNER, simP, nullptr, nullptr,
                       DINNER, N1, N1, S_,
                       (long long)S_ * N1, (long long)S_ * N1, (long long)S_ * S_,
                       scale, 1, 0 };
        gemm_mma_kernel<<<dim3(S_ / BN, S_ / BM, B_), NTH, SMEM_TOTAL>>>(a);
    }

    // 5) softmax -> fp16 probs (fused)
    softmax_kernel<<<dim3(S_, B_), 256>>>(simP, attn);

    // 6) inner = attn @ V -> fp16 only (fused, causal K-limit)
    {
        GemmArgs a = { attn, vt, nullptr, inner, nullptr,
                       S_, S_, S_, DINNER,
                       (long long)S_ * S_, (long long)DINNER * S_,
                       (long long)S_ * DINNER,
                       1.0f, 0, 1 };
        gemm_mma_kernel<<<dim3(DINNER / BN, S_ / BM, B_), NTH, SMEM_TOTAL>>>(a);
    }

    // 7) out = inner @ W_out + b_out (fp32)
    {
        GemmArgs a = { inner, wot, out, nullptr, b_out,
                       DINNER, DINNER, DINNER, DOUT, 0, 0, 0, 1.0f, 0, 0 };
        gemm_mma_kernel<<<dim3(DOUT / BN, M1 / BM, 1), NTH, SMEM_TOTAL>>>(a);
    }
}

// round 10
// speedup vs baseline: 6.3134x; 1.0813x over previous
#include <cuda_runtime.h>
#include <cuda_fp16.h>
#include <cstdint>
#include <float.h>

// ---------------------------------------------------------------------------
// Problem constants
// ---------------------------------------------------------------------------
#define B_     4
#define S_     2048
#define DIN    1024
#define DINNER 1024
#define DOUT   1024
#define M1     (B_ * S_)        // 8192
#define N1     (3 * DINNER)     // 3072

// GEMM tile config (mma.sync)
#define BM 128
#define BN 128
#define BK 64
#define NTH 256                 // 8 warps: 4 (m) x 2 (n)
#define PAD 8
#define LDSROW (BK + PAD)       // 72 fp16 per smem row (144 B)
#define TILE_B (BM * LDSROW * 2)    // 18432 bytes per tile
#define STAGE_B (2 * TILE_B)        // A, B = 36864
#define NSTAGE 3
#define SMEM_TOTAL (NSTAGE * STAGE_B)   // 110592 (108 KB) -> 2 CTAs/SM

// ---------------------------------------------------------------------------
// PTX helpers (all baseline-PTX legal on compute_103)
// ---------------------------------------------------------------------------
__device__ __forceinline__ uint32_t smem_u32(const void* p) {
    uint32_t a;
    asm("{ .reg .u64 t; cvta.to.shared.u64 t, %1; cvt.u32.u64 %0, t; }"
        : "=r"(a) : "l"(p));
    return a;
}

__device__ __forceinline__ void cp_async16(uint32_t dst, const void* src) {
    asm volatile("cp.async.cg.shared.global [%0], [%1], 16;"
                 :: "r"(dst), "l"(src));
}
#define CP_COMMIT() asm volatile("cp.async.commit_group;" ::: "memory")
#define CP_WAIT(n)  asm volatile("cp.async.wait_group %0;" :: "n"(n) : "memory")

__device__ __forceinline__ void ldmat_x4(uint32_t& r0, uint32_t& r1,
                                         uint32_t& r2, uint32_t& r3,
                                         uint32_t addr) {
    asm volatile("ldmatrix.sync.aligned.m8n8.x4.shared.b16 {%0,%1,%2,%3}, [%4];"
                 : "=r"(r0), "=r"(r1), "=r"(r2), "=r"(r3) : "r"(addr));
}

__device__ __forceinline__ void mma_fp16(float* c, const uint32_t* a,
                                         uint32_t b0, uint32_t b1) {
    asm volatile(
        "mma.sync.aligned.m16n8k16.row.col.f32.f16.f16.f32 "
        "{%0,%1,%2,%3}, {%4,%5,%6,%7}, {%8,%9}, {%0,%1,%2,%3};"
        : "+f"(c[0]), "+f"(c[1]), "+f"(c[2]), "+f"(c[3])
        : "r"(a[0]), "r"(a[1]), "r"(a[2]), "r"(a[3]), "r"(b0), "r"(b1));
}

// ---------------------------------------------------------------------------
// Scratch (static device globals)
// ---------------------------------------------------------------------------
__device__ float g_sim[(size_t)B_ * S_ * S_];            // 64 MB fp32

__device__ __half g_xh[(size_t)M1 * DIN];                // 16 MB
__device__ __half g_wqkvt[(size_t)N1 * DIN];             // 6 MB (transposed)
__device__ __half g_woutt[(size_t)DOUT * DINNER];        // 2 MB (transposed)
__device__ __half g_qkvh[(size_t)M1 * N1];               // 48 MB
__device__ __half g_vt[(size_t)B_ * DINNER * S_];        // 16 MB (V^T per batch)
__device__ __half g_attn[(size_t)B_ * S_ * S_];          // 32 MB
__device__ __half g_inner[(size_t)M1 * DINNER];          // 16 MB

// ---------------------------------------------------------------------------
// Conversion kernels
// ---------------------------------------------------------------------------
__global__ void cvt_rm_kernel(const float4* __restrict__ src,
                              __half2* __restrict__ h, long long n4) {
    long long i = (long long)blockIdx.x * blockDim.x + threadIdx.x;
    long long stride = (long long)gridDim.x * blockDim.x;
    for (; i < n4; i += stride) {
        float4 v = src[i];
        h[2 * i]     = __floats2half2_rn(v.x, v.y);
        h[2 * i + 1] = __floats2half2_rn(v.z, v.w);
    }
}

// fp32 [R,C] (row stride sld) -> transposed fp16 [C,R] (row stride dld)
__global__ void cvt_tr_kernel(const float* __restrict__ src,
                              __half* __restrict__ h,
                              int sld, int dld,
                              long long sbatch, long long dbatch) {
    __shared__ float t[32][33];
    const int c0 = blockIdx.x * 32;
    const int r0 = blockIdx.y * 32;
    const long long sb = (long long)blockIdx.z * sbatch;
    const long long db = (long long)blockIdx.z * dbatch;
    const int tx = threadIdx.x, ty = threadIdx.y;

    #pragma unroll
    for (int i = 0; i < 32; i += 8)
        t[ty + i][tx] = src[sb + (long long)(r0 + ty + i) * sld + c0 + tx];
    __syncthreads();
    #pragma unroll
    for (int i = 0; i < 32; i += 8) {
        long long o = db + (long long)(c0 + ty + i) * dld + r0 + tx;
        h[o] = __float2half(t[tx][ty + i]);
    }
}

// fp16 [R,C] (row stride sld) -> transposed fp16 [C,R] (row stride dld)
__global__ void cvt_tr_half_kernel(const __half* __restrict__ src,
                                   __half* __restrict__ h,
                                   int sld, int dld,
                                   long long sbatch, long long dbatch) {
    __shared__ __half t[32][33];
    const int c0 = blockIdx.x * 32;
    const int r0 = blockIdx.y * 32;
    const long long sb = (long long)blockIdx.z * sbatch;
    const long long db = (long long)blockIdx.z * dbatch;
    const int tx = threadIdx.x, ty = threadIdx.y;

    #pragma unroll
    for (int i = 0; i < 32; i += 8)
        t[ty + i][tx] = src[sb + (long long)(r0 + ty + i) * sld + c0 + tx];
    __syncthreads();
    #pragma unroll
    for (int i = 0; i < 32; i += 8) {
        long long o = db + (long long)(c0 + ty + i) * dld + r0 + tx;
        h[o] = t[tx][ty + i];
    }
}

// ---------------------------------------------------------------------------
// mma.sync fp16 GEMM: C[M,N] = scale * sum_k A[m,k]*B[n,k] (+bias)
// A: [M,K] K-contiguous ; B: [N,K] K-contiguous
// BK=64, 3-stage cp.async ring, 1 barrier/chunk, software-pipelined fragments.
// ---------------------------------------------------------------------------
struct GemmArgs {
    const __half *A, *B;
    float* C;                    // nullable fp32 out
    __half* Ch;                  // nullable fp16 out
    const float* bias;           // nullable
    int K, lda, ldb, ldc;
    long long strideA, strideB, strideC;
    float scale;
    int causal_skip;             // skip CTA if bx > by
    int kmax_mode;               // K_eff = min(K, (by+1)*BM)
};

__device__ __forceinline__ void load_tile(const __half* __restrict__ g,
                                          int row0, int ld, int k0, uint32_t sm) {
    const int tid = threadIdx.x;
    #pragma unroll
    for (int t = 0; t < 4; t++) {
        int idx = t * NTH + tid;        // 0..1023
        int r  = idx >> 3;              // 0..127
        int kc = (idx & 7) * 8;         // 0..56
        cp_async16(sm + (uint32_t)(r * LDSROW + kc) * 2,
                   g + (long long)(row0 + r) * ld + k0 + kc);
    }
}

__global__ void __launch_bounds__(NTH, 2)
gemm_mma_kernel(GemmArgs args)
{
    const int bx = blockIdx.x, by = blockIdx.y, bb = blockIdx.z;
    if (args.causal_skip && bx > by) return;

    extern __shared__ char smem[];
    const uint32_t smem_base = smem_u32(smem);

    const int tid = threadIdx.x;
    const int wid = tid >> 5;
    const int lane = tid & 31;
    const int wm = wid >> 1;            // 0..3  (32-row slab)
    const int wn = wid & 1;             // 0..1  (64-col slab)
    const int lrow = lane & 15;         // ldmatrix row select
    const int lcol = (lane >> 4) * 8;   // ldmatrix k-half select

    const __half* A = args.A + (long long)bb * args.strideA;
    const __half* B = args.B + (long long)bb * args.strideB;

    const int Keff = args.kmax_mode ? min(args.K, (by + 1) * BM) : args.K;
    const int nch = Keff / BK;
    const int arow = by * BM;
    const int brow = bx * BN;

    float acc[2][8][4];
    #pragma unroll
    for (int i = 0; i < 2; i++)
        #pragma unroll
        for (int j = 0; j < 8; j++)
            #pragma unroll
            for (int k = 0; k < 4; k++) acc[i][j][k] = 0.f;

    // prologue: chunks 0,1 -> stages 0,1
    load_tile(A, arow, args.lda, 0, smem_base);
    load_tile(B, brow, args.ldb, 0, smem_base + TILE_B);
    CP_COMMIT();
    if (nch > 1) {
        load_tile(A, arow, args.lda, BK, smem_base + STAGE_B);
        load_tile(B, brow, args.ldb, BK, smem_base + STAGE_B + TILE_B);
        CP_COMMIT();
    }

    // per-warp base offsets (loop-invariant)
    const uint32_t a_off0 = (uint32_t)((wm * 32 + lrow) * LDSROW) * 2 + lcol * 2;
    const uint32_t b_off0 = (uint32_t)((wn * 64 + lrow) * LDSROW) * 2 + lcol * 2;

    for (int c = 0; c < nch; c++) {
        // chunk c resident (1 group may stay in flight mid-stream)
        if (c < nch - 1) { CP_WAIT(1); } else { CP_WAIT(0); }
        __syncthreads();     // publish chunk c; stage (c+2)%3 free for overwrite

        // prefetch chunk c+2 into stage (c+2)%3
        if (c + 2 < nch) {
            const uint32_t sq = smem_base + ((c + 2) % NSTAGE) * STAGE_B;
            const int k0 = (c + 2) * BK;
            load_tile(A, arow, args.lda, k0, sq);
            load_tile(B, brow, args.ldb, k0, sq + TILE_B);
            CP_COMMIT();
        }

        const uint32_t sp = smem_base + (c % NSTAGE) * STAGE_B;
        const uint32_t a_base = sp + a_off0;
        const uint32_t b_base = sp + TILE_B + b_off0;

        // ---- software-pipelined 8 phases: (kk 0..3) x (jg 0..1) ----
        uint32_t Abuf[2][8];   // [buf][mi*4 + r]
        uint32_t Bbuf[2][8];   // [buf][b0 x4, b1 x4]

        // preload phase 0 fragments: A(kk=0), B(kk=0, jg=0)
        {
            ldmat_x4(Abuf[0][0], Abuf[0][1], Abuf[0][2], Abuf[0][3], a_base);
            ldmat_x4(Abuf[0][4], Abuf[0][5], Abuf[0][6], Abuf[0][7],
                     a_base + (uint32_t)(16 * LDSROW) * 2);
            #pragma unroll
            for (int np = 0; np < 2; np++) {
                uint32_t r0, r1, r2, r3;
                ldmat_x4(r0, r1, r2, r3,
                         b_base + (uint32_t)(np * 16 * LDSROW) * 2);
                Bbuf[0][np * 2]     = r0; Bbuf[0][4 + np * 2]     = r2;
                Bbuf[0][np * 2 + 1] = r1; Bbuf[0][4 + np * 2 + 1] = r3;
            }
        }

        #pragma unroll
        for (int ph = 0; ph < 8; ph++) {
            const int kk = ph >> 1;
            const int jg = ph & 1;
            const int ab = kk & 1;
            const int bbuf = ph & 1;

            // prefetch next phase's fragments
            if (ph < 7) {
                const int nkk = (ph + 1) >> 1;
                const int njg = (ph + 1) & 1;
                const uint32_t nkoff = (uint32_t)(nkk * 16) * 2;
                if (njg == 0) {   // new kk: load A(nkk)
                    const int nab = nkk & 1;
                    ldmat_x4(Abuf[nab][0], Abuf[nab][1], Abuf[nab][2], Abuf[nab][3],
                             a_base + nkoff);
                    ldmat_x4(Abuf[nab][4], Abuf[nab][5], Abuf[nab][6], Abuf[nab][7],
                             a_base + (uint32_t)(16 * LDSROW) * 2 + nkoff);
                }
                const int nbb = (ph + 1) & 1;
                #pragma unroll
                for (int np = 0; np < 2; np++) {
                    uint32_t r0, r1, r2, r3;
                    ldmat_x4(r0, r1, r2, r3,
                             b_base + (uint32_t)((njg * 2 + np) * 16 * LDSROW) * 2
                                    + nkoff);
                    Bbuf[nbb][np * 2]     = r0; Bbuf[nbb][4 + np * 2]     = r2;
                    Bbuf[nbb][np * 2 + 1] = r1; Bbuf[nbb][4 + np * 2 + 1] = r3;
                }
            }

            // 8 MMAs for this phase
            #pragma unroll
            for (int mi = 0; mi < 2; mi++)
                #pragma unroll
                for (int jl = 0; jl < 4; jl++)
                    mma_fp16(acc[mi][jg * 4 + jl], &Abuf[ab][mi * 4],
                             Bbuf[bbuf][jl], Bbuf[bbuf][4 + jl]);
        }
    }

    // epilogue (acc is thread-private; no sync needed)
    float* C = args.C ? args.C + (long long)bb * args.strideC : nullptr;
    __half* Ch = args.Ch ? args.Ch + (long long)bb * args.strideC : nullptr;
    const int g = lane >> 2;
    const int tig = lane & 3;

    #pragma unroll
    for (int mi = 0; mi < 2; mi++) {
        #pragma unroll
        for (int j = 0; j < 8; j++) {
            const int row0 = arow + wm * 32 + mi * 16 + g;
            const int col0 = brow + wn * 64 + j * 8 + 2 * tig;
            float v[4];
            #pragma unroll
            for (int k = 0; k < 4; k++) v[k] = acc[mi][j][k] * args.scale;
            if (args.bias) {
                v[0] += args.bias[col0];     v[1] += args.bias[col0 + 1];
                v[2] += args.bias[col0];     v[3] += args.bias[col0 + 1];
            }
            const long long o0 = (long long)row0 * args.ldc + col0;
            const long long o1 = (long long)(row0 + 8) * args.ldc + col0;
            if (C) {
                C[o0] = v[0]; C[o0 + 1] = v[1];
                C[o1] = v[2]; C[o1 + 1] = v[3];
            }
            if (Ch) {
                *(__half2*)(Ch + o0) = __floats2half2_rn(v[0], v[1]);
                *(__half2*)(Ch + o1) = __floats2half2_rn(v[2], v[3]);
            }
        }
    }
}

// ---------------------------------------------------------------------------
// Causal row softmax: fp32 sim -> fp16 probs, zero-filled to 128-block edge
// ---------------------------------------------------------------------------
__global__ void __launch_bounds__(256)
softmax_kernel(const float* __restrict__ sim, __half* __restrict__ ph)
{
    const int i = blockIdx.x;
    const int b = blockIdx.y;
    const float* row = sim + ((size_t)b * S_ + i) * S_;
    __half* rh = ph + ((size_t)b * S_ + i) * S_;
    const int n = i + 1;

    __shared__ float red[256];
    const int t = threadIdx.x;

    float m = -FLT_MAX;
    for (int j = t; j < n; j += 256) m = fmaxf(m, row[j]);
    red[t] = m; __syncthreads();
    for (int s = 128; s > 0; s >>= 1) {
        if (t < s) red[t] = fmaxf(red[t], red[t + s]);
        __syncthreads();
    }
    m = red[0]; __syncthreads();

    float sum = 0.f;
    for (int j = t; j < n; j += 256) sum += expf(row[j] - m);
    red[t] = sum; __syncthreads();
    for (int s = 128; s > 0; s >>= 1) {
        if (t < s) red[t] += red[t + s];
        __syncthreads();
    }
    const float inv = 1.f / red[0];
    __syncthreads();

    for (int j = t; j < n; j += 256)
        rh[j] = __float2half(expf(row[j] - m) * inv);
    const int pad_end = min(S_, ((n + BM - 1) / BM) * BM);
    for (int j = n + t; j < pad_end; j += 256)
        rh[j] = __float2half(0.f);
}

// ---------------------------------------------------------------------------
// Launch
// ---------------------------------------------------------------------------
static void* sym(const void* s) { void* p; cudaGetSymbolAddress(&p, s); return p; }

extern "C" void kernel_launch(void* const* d_in, const int* in_sizes, int n_in,
                              void* d_out, int out_size)
{
    const float* x     = (const float*)d_in[0];
    const float* w_qkv = (const float*)d_in[1];
    const float* w_out = (const float*)d_in[2];
    const float* b_out = (const float*)d_in[3];
    float* out = (float*)d_out;

    float* simP = (float*)sym(g_sim);
    __half* xh    = (__half*)sym(g_xh);
    __half* wqt   = (__half*)sym(g_wqkvt);
    __half* wot   = (__half*)sym(g_woutt);
    __half* qkvh  = (__half*)sym(g_qkvh);
    __half* vt    = (__half*)sym(g_vt);
    __half* attn  = (__half*)sym(g_attn);
    __half* inner = (__half*)sym(g_inner);

    cudaFuncSetAttribute(gemm_mma_kernel,
                         cudaFuncAttributeMaxDynamicSharedMemorySize, SMEM_TOTAL);

    const float scale = 1.0f / 32.0f;   // DIM_INNER^-0.5

    // 1) input conversion / weight transposes
    cvt_rm_kernel<<<2048, 256>>>((const float4*)x, (__half2*)xh,
                                 (long long)M1 * DIN / 4);
    cvt_tr_kernel<<<dim3(N1 / 32, DIN / 32, 1), dim3(32, 8)>>>(
        w_qkv, wqt, N1, DIN, 0, 0);
    cvt_tr_kernel<<<dim3(DOUT / 32, DINNER / 32, 1), dim3(32, 8)>>>(
        w_out, wot, DOUT, DINNER, 0, 0);

    // 2) QKV projection -> fp16 qkvh only (no fp32 copy)
    {
        GemmArgs a = { xh, wqt, nullptr, qkvh, nullptr,
                       DIN, DIN, DIN, N1, 0, 0, 0, 1.0f, 0, 0 };
        gemm_mma_kernel<<<dim3(N1 / BN, M1 / BM, 1), NTH, SMEM_TOTAL>>>(a);
    }

    // 3) V transpose (per batch), fp16 -> fp16
    cvt_tr_half_kernel<<<dim3(DINNER / 32, S_ / 32, B_), dim3(32, 8)>>>(
        qkvh + 2 * DINNER, vt, N1, S_,
        (long long)S_ * N1, (long long)DINNER * S_);

    // 4) sim = scale * Q K^T (causal blocks only), fp32
    {
        GemmArgs a = { qkvh, qkvh + DINNER, simP, nullptr, nullptr,
                       DINNER, N1, N1, S_,
                       (long long)S_ * N1, (long long)S_ * N1, (long long)S_ * S_,
                       scale, 1, 0 };
        gemm_mma_kernel<<<dim3(S_ / BN, S_ / BM, B_), NTH, SMEM_TOTAL>>>(a);
    }

    // 5) softmax -> fp16 probs (fused)
    softmax_kernel<<<dim3(S_, B_), 256>>>(simP, attn);

    // 6) inner = attn @ V -> fp16 only (fused, causal K-limit)
    {
        GemmArgs a = { attn, vt, nullptr, inner, nullptr,
                       S_, S_, S_, DINNER,
                       (long long)S_ * S_, (long long)DINNER * S_,
                       (long long)S_ * DINNER,
                       1.0f, 0, 1 };
        gemm_mma_kernel<<<dim3(DINNER / BN, S_ / BM, B_), NTH, SMEM_TOTAL>>>(a);
    }

    // 7) out = inner @ W_out + b_out (fp32)
    {
        GemmArgs a = { inner, wot, out, nullptr, b_out,
                       DINNER, DINNER, DINNER, DOUT, 0, 0, 0, 1.0f, 0, 0 };
        gemm_mma_kernel<<<dim3(DOUT / BN, M1 / BM, 1), NTH, SMEM_TOTAL>>>(a);
    }
}